// round 14
// baseline (speedup 1.0000x reference)
#include <cuda_runtime.h>
#include <cuda_bf16.h>
#include <math.h>
#include <stdint.h>

// ---------------- problem constants ----------------
#define BATCH  8
#define HGc    17
#define WGc    90
#define Lseq   1530            // HG*WG
#define Tseq   6120            // 4*L
#define BT     48960           // BATCH*Tseq
#define DMc    128
#define EXPC   256
#define NHC    4
#define HDC    64
#define PHc    20
#define PWc    8
#define CINc   3
#define NPATCH 12240           // BATCH*Lseq
#define PROJW  768             // gate(256)+xBC(512); dt separate
#define SEGS   8
#define QSEG   765             // Tseq / SEGS

// ---------------- device scratch (static, no allocs) ----------------
__device__ float g_h      [(size_t)BT * DMc];
__device__ float g_hn     [(size_t)BT * DMc];
__device__ float g_proj   [(size_t)BT * PROJW];
__device__ float g_xbc    [(size_t)BT * 512];
__device__ float g_dt     [(size_t)BT * NHC];
__device__ float g_dA     [(size_t)BT * NHC];
__device__ float g_dtx    [(size_t)BT * EXPC];
__device__ float g_y      [(size_t)BT * EXPC];
__device__ float g_e      [(size_t)32 * Tseq];                 // cumprod dA per (b,h)
__device__ float g_spart  [(size_t)32 * SEGS * 64 * 128];      // segment-final partial states
__device__ float g_sinit  [(size_t)32 * SEGS * 64 * 128];      // segment initial states
// bf16 split operand buffers for tensor-core GEMMs
__device__ __nv_bfloat16 g_ahi[(size_t)BT * 256];
__device__ __nv_bfloat16 g_alo[(size_t)BT * 256];
__device__ __nv_bfloat16 g_whi[(size_t)768 * 256];      // patch-embed weight
__device__ __nv_bfloat16 g_wlo[(size_t)768 * 256];
__device__ __nv_bfloat16 g_wihi[(size_t)4 * 772 * DMc]; // in_proj weights (all layers)
__device__ __nv_bfloat16 g_wilo[(size_t)4 * 772 * DMc];
__device__ __nv_bfloat16 g_wohi[(size_t)4 * DMc * EXPC];// out_proj weights (all layers)
__device__ __nv_bfloat16 g_wolo[(size_t)4 * DMc * EXPC];
__device__ __nv_bfloat16 g_r1hi[DMc * DMc];
__device__ __nv_bfloat16 g_r1lo[DMc * DMc];
__device__ __nv_bfloat16 g_r2hi[480 * DMc];
__device__ __nv_bfloat16 g_r2lo[480 * DMc];
__device__ __nv_bfloat16 g_bhi[(size_t)NPATCH * DMc];
__device__ __nv_bfloat16 g_blo[(size_t)NPATCH * DMc];
__device__ __nv_bfloat16 g_pathi[(size_t)NPATCH * 512];
__device__ __nv_bfloat16 g_patlo[(size_t)NPATCH * 512];

__device__ __forceinline__ uint32_t smem_u32(const void* p)
{
    uint32_t a;
    asm("{ .reg .u64 t; cvta.to.shared.u64 t, %1; cvt.u32.u64 %0, t; }"
        : "=r"(a) : "l"(p));
    return a;
}

__device__ __forceinline__ void ldmx4(uint32_t& r0, uint32_t& r1, uint32_t& r2,
                                      uint32_t& r3, uint32_t addr)
{
    asm volatile("ldmatrix.sync.aligned.m8n8.x4.shared.b16 {%0,%1,%2,%3}, [%4];"
                 : "=r"(r0), "=r"(r1), "=r"(r2), "=r"(r3) : "r"(addr));
}

__device__ __forceinline__ void mma_bf16(float* d, const uint32_t* a, const uint32_t* b)
{
    asm volatile(
        "mma.sync.aligned.m16n8k16.row.col.f32.bf16.bf16.f32 "
        "{%0,%1,%2,%3}, {%4,%5,%6,%7}, {%8,%9}, {%0,%1,%2,%3};"
        : "+f"(d[0]), "+f"(d[1]), "+f"(d[2]), "+f"(d[3])
        : "r"(a[0]), "r"(a[1]), "r"(a[2]), "r"(a[3]), "r"(b[0]), "r"(b[1]));
}

__device__ __forceinline__ void cpa16(uint32_t dst, const void* src, bool pred)
{
    int sz = pred ? 16 : 0;
    asm volatile("cp.async.cg.shared.global [%0], [%1], 16, %2;"
                 :: "r"(dst), "l"(src), "r"(sz) : "memory");
}
#define CP_COMMIT() asm volatile("cp.async.commit_group;" ::: "memory")
#define CP_WAIT(n)  asm volatile("cp.async.wait_group %0;" :: "n"(n) : "memory")

// ---------------- f32x2 helpers ----------------
union F4U { float4 f; unsigned long long u[2]; float s[4]; };

__device__ __forceinline__ unsigned long long ffma2(unsigned long long a,
                                                    unsigned long long b,
                                                    unsigned long long c)
{
    unsigned long long d;
    asm("fma.rn.f32x2 %0, %1, %2, %3;" : "=l"(d) : "l"(a), "l"(b), "l"(c));
    return d;
}

__device__ __forceinline__ unsigned long long fmul2(unsigned long long a,
                                                    unsigned long long b)
{
    unsigned long long d;
    asm("mul.rn.f32x2 %0, %1, %2;" : "=l"(d) : "l"(a), "l"(b));
    return d;
}

__device__ __forceinline__ unsigned long long pack2(float lo, float hi)
{
    unsigned long long d;
    asm("mov.b64 %0, {%1, %2};" : "=l"(d) : "f"(lo), "f"(hi));
    return d;
}

__device__ __forceinline__ void unpack2(unsigned long long v, float& lo, float& hi)
{
    asm("mov.b64 {%0, %1}, %2;" : "=f"(lo), "=f"(hi) : "l"(v));
}

// ---------------- pack 4 floats -> 4 bf16 hi + 4 bf16 lo stores ----------------
__device__ __forceinline__ void store_split4(__nv_bfloat16* hi_dst, __nv_bfloat16* lo_dst,
                                             float4 v)
{
    __nv_bfloat16 hh[4], ll[4];
    float vs[4] = {v.x, v.y, v.z, v.w};
#pragma unroll
    for (int i = 0; i < 4; i++) {
        hh[i] = __float2bfloat16(vs[i]);
        ll[i] = __float2bfloat16(vs[i] - __bfloat162float(hh[i]));
    }
    *(uint2*)hi_dst = *(uint2*)hh;
    *(uint2*)lo_dst = *(uint2*)ll;
}

// ---------------- bf16-split tensor-core GEMM (mma.sync, cp.async pipelined) ----------------
// mode 0: C = A@W^T + bias (+resid)
// mode 1: gelu(A@W^T + bias) -> bf16 hi/lo split into g_bhi/g_blo (C unused)
// mode 2: A@W^T + bias scattered into 4 directional rows of C (=g_h)
#define MLDS 72   // smem row pitch in bf16 (144 bytes)
#define STGB (4 * 128 * MLDS * 2)   // bytes per pipeline stage
#define RB   (128 * MLDS * 2)       // bytes per region within stage
#define MMA_SMEM (2 * STGB)

__device__ __forceinline__ void epi_store(int mode, float* C, int ldc,
                                          const float* resid, int row, int col,
                                          float vx, float vy)
{
    if (mode == 1) {
        __nv_bfloat16 hx = __float2bfloat16(vx);
        __nv_bfloat16 hy = __float2bfloat16(vy);
        g_bhi[(size_t)row * ldc + col] = hx;
        g_bhi[(size_t)row * ldc + col + 1] = hy;
        g_blo[(size_t)row * ldc + col] = __float2bfloat16(vx - __bfloat162float(hx));
        g_blo[(size_t)row * ldc + col + 1] = __float2bfloat16(vy - __bfloat162float(hy));
    } else if (mode == 2) {
        int b = row / Lseq, l = row % Lseq;
        int hg = l / WGc, wg = l % WGc;
        int j = wg * HGc + hg;
        size_t base = (size_t)b * Tseq;
        float2 v = make_float2(vx, vy);
        *(float2*)(C + (base + l) * DMc + col) = v;
        *(float2*)(C + (base + Lseq + j) * DMc + col) = v;
        *(float2*)(C + (base + 2 * Lseq + (Lseq - 1 - l)) * DMc + col) = v;
        *(float2*)(C + (base + 3 * Lseq + (Lseq - 1 - j)) * DMc + col) = v;
    } else {
        if (resid) {
            vx += resid[(size_t)row * ldc + col];
            vy += resid[(size_t)row * ldc + col + 1];
        }
        *(float2*)(C + (size_t)row * ldc + col) = make_float2(vx, vy);
    }
}

__global__ __launch_bounds__(256)
void mma_gemm(const __nv_bfloat16* __restrict__ Ahi, const __nv_bfloat16* __restrict__ Alo,
              const __nv_bfloat16* __restrict__ Whi, const __nv_bfloat16* __restrict__ Wlo,
              const float* __restrict__ bias, const float* __restrict__ resid,
              float* __restrict__ C, int M, int Ktot, int N, int ldc, int mode)
{
    extern __shared__ __align__(16) char sm[];
    const uint32_t base = smem_u32(sm);

    const int tid  = threadIdx.x;
    const int wid  = tid >> 5;
    const int lane = tid & 31;
    const int m0 = blockIdx.y * 128;
    const int n0 = blockIdx.x * 128;
    const int wm = (wid >> 2) * 64;
    const int wn = (wid & 3) * 32;

    float acc[4][4][4];
#pragma unroll
    for (int i = 0; i < 4; i++)
#pragma unroll
        for (int j = 0; j < 4; j++)
#pragma unroll
            for (int q = 0; q < 4; q++) acc[i][j][q] = 0.f;

    const int lrow = tid >> 1;
    const int lcol = (tid & 1) * 32;
    const bool okA = (m0 + lrow) < M;
    const bool okW = (n0 + lrow) < N;
    const int lm_row = lane & 15;
    const int lm_col = (lane >> 4) * 8;
    const uint32_t wr = (uint32_t)((lrow * MLDS + lcol) * 2);

    const __nv_bfloat16* gAh = Ahi + (size_t)(m0 + lrow) * Ktot + lcol;
    const __nv_bfloat16* gAl = Alo + (size_t)(m0 + lrow) * Ktot + lcol;
    const __nv_bfloat16* gWh = Whi + (size_t)(n0 + lrow) * Ktot + lcol;
    const __nv_bfloat16* gWl = Wlo + (size_t)(n0 + lrow) * Ktot + lcol;

    const int nch = Ktot / 64;

    // prefetch chunk 0 into stage 0
    {
        uint32_t so = base;
#pragma unroll
        for (int q = 0; q < 4; q++) {
            cpa16(so + wr + q * 16,          gAh + q * 8, okA);
            cpa16(so + RB + wr + q * 16,     gAl + q * 8, okA);
            cpa16(so + 2 * RB + wr + q * 16, gWh + q * 8, okW);
            cpa16(so + 3 * RB + wr + q * 16, gWl + q * 8, okW);
        }
        CP_COMMIT();
    }

    for (int ch = 0; ch < nch; ch++) {
        if (ch + 1 < nch) {
            uint32_t so = base + (uint32_t)((ch + 1) & 1) * STGB;
            int kof = (ch + 1) * 64;
#pragma unroll
            for (int q = 0; q < 4; q++) {
                cpa16(so + wr + q * 16,          gAh + kof + q * 8, okA);
                cpa16(so + RB + wr + q * 16,     gAl + kof + q * 8, okA);
                cpa16(so + 2 * RB + wr + q * 16, gWh + kof + q * 8, okW);
                cpa16(so + 3 * RB + wr + q * 16, gWl + kof + q * 8, okW);
            }
            CP_COMMIT();
            CP_WAIT(1);
        } else {
            CP_WAIT(0);
        }
        __syncthreads();

        const uint32_t sb  = base + (uint32_t)(ch & 1) * STGB;
        const uint32_t bAh = sb;
        const uint32_t bAl = sb + RB;
        const uint32_t bWh = sb + 2 * RB;
        const uint32_t bWl = sb + 3 * RB;

#pragma unroll
        for (int ks = 0; ks < 4; ks++) {
            const int k0 = ks * 16;
            uint32_t bh[4][2], bl[4][2];
#pragma unroll
            for (int pr = 0; pr < 2; pr++) {
                uint32_t off = (uint32_t)(((wn + pr * 16 + lm_row) * MLDS + k0 + lm_col) * 2);
                uint32_t r0, r1, r2, r3;
                ldmx4(r0, r1, r2, r3, bWh + off);
                bh[pr * 2][0] = r0; bh[pr * 2 + 1][0] = r1;
                bh[pr * 2][1] = r2; bh[pr * 2 + 1][1] = r3;
                ldmx4(r0, r1, r2, r3, bWl + off);
                bl[pr * 2][0] = r0; bl[pr * 2 + 1][0] = r1;
                bl[pr * 2][1] = r2; bl[pr * 2 + 1][1] = r3;
            }
#pragma unroll
            for (int mt = 0; mt < 4; mt++) {
                uint32_t off = (uint32_t)(((wm + mt * 16 + lm_row) * MLDS + k0 + lm_col) * 2);
                uint32_t ah[4], al[4];
                ldmx4(ah[0], ah[1], ah[2], ah[3], bAh + off);
                ldmx4(al[0], al[1], al[2], al[3], bAl + off);
#pragma unroll
                for (int nt = 0; nt < 4; nt++) {
                    mma_bf16(acc[mt][nt], ah, bh[nt]);
                    mma_bf16(acc[mt][nt], ah, bl[nt]);
                    mma_bf16(acc[mt][nt], al, bh[nt]);
                }
            }
        }
        __syncthreads();
    }

    const int gid = lane >> 2;
    const int tig = lane & 3;
#pragma unroll
    for (int mt = 0; mt < 4; mt++) {
        int row0 = m0 + wm + mt * 16 + gid;
        int row1 = row0 + 8;
#pragma unroll
        for (int nt = 0; nt < 4; nt++) {
            int col = n0 + wn + nt * 8 + tig * 2;
            if (col >= N) continue;
            float bx = bias[col];
            float by = bias[col + 1];
            if (row0 < M) {
                float vx = acc[mt][nt][0] + bx, vy = acc[mt][nt][1] + by;
                if (mode == 1) {
                    vx = 0.5f * vx * (1.f + erff(vx * 0.7071067811865475f));
                    vy = 0.5f * vy * (1.f + erff(vy * 0.7071067811865475f));
                }
                epi_store(mode, C, ldc, resid, row0, col, vx, vy);
            }
            if (row1 < M) {
                float vx = acc[mt][nt][2] + bx, vy = acc[mt][nt][3] + by;
                if (mode == 1) {
                    vx = 0.5f * vx * (1.f + erff(vx * 0.7071067811865475f));
                    vy = 0.5f * vy * (1.f + erff(vy * 0.7071067811865475f));
                }
                epi_store(mode, C, ldc, resid, row1, col, vx, vy);
            }
        }
    }
}

// ---------------- weight fp32 -> bf16 hi/lo split (generic dst) ----------------
__global__ void wsplit(const float* __restrict__ w, __nv_bfloat16* __restrict__ hi,
                       __nv_bfloat16* __restrict__ lo, int total)
{
    int idx = blockIdx.x * blockDim.x + threadIdx.x;
    if (idx >= total) return;
    float v = w[idx];
    __nv_bfloat16 h = __float2bfloat16(v);
    hi[idx] = h;
    lo[idx] = __float2bfloat16(v - __bfloat162float(h));
}

__global__ void wconv_pad(const float* __restrict__ w, int N, int Ksrc, int Kdst)
{
    int idx = blockIdx.x * blockDim.x + threadIdx.x;
    if (idx >= N * Kdst) return;
    int k = idx % Kdst, n = idx / Kdst;
    float v = (k < Ksrc) ? w[n * Ksrc + k] : 0.f;
    __nv_bfloat16 hi = __float2bfloat16(v);
    g_whi[idx] = hi;
    g_wlo[idx] = __float2bfloat16(v - __bfloat162float(hi));
}

// ---------------- patch gather (bf16 split, K padded 480->512) ----------------
__global__ void patch_gather(const float* __restrict__ x)
{
    int idx = blockIdx.x * blockDim.x + threadIdx.x;
    if (idx >= NPATCH * 512) return;
    int q  = idx & 511;
    int bl = idx >> 9;
    float v = 0.f;
    if (q < 480) {
        int c = q / 160, rr = q % 160;
        int i = rr / PWc, jj = rr % PWc;
        int b = bl / Lseq, l = bl % Lseq;
        int hg = l / WGc, wg = l % WGc;
        v = x[(((size_t)(b * CINc + c) * 340) + hg * PHc + i) * 720 + wg * PWc + jj];
    }
    __nv_bfloat16 hi = __float2bfloat16(v);
    g_pathi[idx] = hi;
    g_patlo[idx] = __float2bfloat16(v - __bfloat162float(hi));
}

// ---------------- rmsnorm: warp per row, float4 per lane, fused dt head ----------------
__global__ __launch_bounds__(256)
void rmsnorm128(const float* __restrict__ X, const float* __restrict__ w,
                float* __restrict__ Y, int emit_bf16,
                const float* __restrict__ wdt, const float* __restrict__ inb,
                const float* __restrict__ dtb, const float* __restrict__ alog)
{
    int wid  = threadIdx.x >> 5;
    int lane = threadIdx.x & 31;
    int row  = blockIdx.x * 8 + wid;
    float4 vx = *(const float4*)(X + (size_t)row * DMc + lane * 4);
    float s = vx.x * vx.x + vx.y * vx.y + vx.z * vx.z + vx.w * vx.w;
#pragma unroll
    for (int o = 16; o > 0; o >>= 1) s += __shfl_xor_sync(0xffffffffu, s, o);
    float sc = rsqrtf(s * (1.f / DMc) + 1e-5f);
    float4 wv = *(const float4*)(w + lane * 4);
    float4 o4 = make_float4(vx.x * sc * wv.x, vx.y * sc * wv.y,
                            vx.z * sc * wv.z, vx.w * sc * wv.w);
    if (Y) *(float4*)(Y + (size_t)row * DMc + lane * 4) = o4;
    if (emit_bf16)
        store_split4(g_ahi + (size_t)row * DMc + lane * 4,
                     g_alo + (size_t)row * DMc + lane * 4, o4);
    if (wdt) {
        float dts[4];
#pragma unroll
        for (int h = 0; h < 4; h++) {
            float4 q = *(const float4*)(wdt + h * DMc + lane * 4);
            float t = o4.x * q.x + o4.y * q.y + o4.z * q.z + o4.w * q.w;
#pragma unroll
            for (int o = 16; o > 0; o >>= 1) t += __shfl_xor_sync(0xffffffffu, t, o);
            dts[h] = t;
        }
        if (lane == 0) {
#pragma unroll
            for (int h = 0; h < 4; h++) {
                float xv = dts[h] + inb[768 + h] + dtb[h];
                float sp = (xv > 20.f) ? xv : log1pf(expf(xv));
                g_dt[row * 4 + h] = sp;
                g_dA[row * 4 + h] = expf(-expf(alog[h]) * sp);
            }
        }
    }
}

// ---------------- conv(K=4)+silu, time-tiled x4, fused dtx ----------------
__global__ void conv_silu(const float* __restrict__ cw, const float* __restrict__ cb)
{
    int idx = blockIdx.x * blockDim.x + threadIdx.x;   // (BT/4)*128
    if (idx >= (BT / 4) * 128) return;
    int c4 = idx & 127;
    int q4 = idx >> 7;
    int tq = q4 % (Tseq / 4), b = q4 / (Tseq / 4);
    int t0 = tq * 4;
    int c = c4 * 4;
    float4 bias = *(const float4*)(cb + c);
    float4 w0 = *(const float4*)(cw + (c + 0) * 4);
    float4 w1 = *(const float4*)(cw + (c + 1) * 4);
    float4 w2 = *(const float4*)(cw + (c + 2) * 4);
    float4 w3 = *(const float4*)(cw + (c + 3) * 4);
    const float* base = g_proj + ((size_t)(b * Tseq + t0)) * PROJW + 256 + c;
    float4 in[7];
#pragma unroll
    for (int k = 0; k < 7; k++) {
        int tt = t0 + k - 3;
        in[k] = (tt >= 0) ? *(const float4*)(base + (ptrdiff_t)(k - 3) * PROJW)
                          : make_float4(0.f, 0.f, 0.f, 0.f);
    }
    size_t bt0 = (size_t)b * Tseq + t0;
#pragma unroll
    for (int q = 0; q < 4; q++) {
        float4 acc = bias;
#pragma unroll
        for (int k = 0; k < 4; k++) {
            float4 v = in[q + k];
            acc.x = fmaf(v.x, ((const float*)&w0)[k], acc.x);
            acc.y = fmaf(v.y, ((const float*)&w1)[k], acc.y);
            acc.z = fmaf(v.z, ((const float*)&w2)[k], acc.z);
            acc.w = fmaf(v.w, ((const float*)&w3)[k], acc.w);
        }
        float4 val;
        val.x = acc.x / (1.f + expf(-acc.x));
        val.y = acc.y / (1.f + expf(-acc.y));
        val.z = acc.z / (1.f + expf(-acc.z));
        val.w = acc.w / (1.f + expf(-acc.w));
        *(float4*)(g_xbc + (bt0 + q) * 512 + c) = val;
        if (c4 < 64) {
            float dtv = g_dt[(bt0 + q) * 4 + (c4 >> 4)];
            *(float4*)(g_dtx + (bt0 + q) * EXPC + c) =
                make_float4(val.x * dtv, val.y * dtv, val.z * dtv, val.w * dtv);
        }
    }
}

// ---------------- cumprod of dA within each segment ----------------
__global__ void e_kernel()
{
    int gw   = blockIdx.x * 8 + (threadIdx.x >> 5);   // 0..255 = bh(32) x seg(8)
    int lane = threadIdx.x & 31;
    int bh = gw >> 3, seg = gw & 7;
    int b = bh >> 2, h = bh & 3;
    size_t dbase = ((size_t)b * Tseq + seg * QSEG) * 4 + h;
    float v[24];
    float prod = 1.f;
#pragma unroll
    for (int i = 0; i < 24; i++) {
        int t = lane * 24 + i;
        float d = (t < QSEG) ? g_dA[dbase + (size_t)t * 4] : 1.f;
        prod *= d;
        v[i] = prod;
    }
    float inc = prod;
#pragma unroll
    for (int o = 1; o < 32; o <<= 1) {
        float q = __shfl_up_sync(0xffffffffu, inc, o);
        if (lane >= o) inc *= q;
    }
    float exs = __shfl_up_sync(0xffffffffu, inc, 1);
    if (lane == 0) exs = 1.f;
    size_t ebase = (size_t)bh * Tseq + seg * QSEG;
#pragma unroll
    for (int i = 0; i < 24; i++) {
        int t = lane * 24 + i;
        if (t < QSEG) g_e[ebase + t] = exs * v[i];
    }
}

// ---------------- scan step body (packed f32x2) ----------------
__device__ __forceinline__ void scan_step(unsigned long long s[4][2],
                                          const F4U& bn, const F4U& cn, const F4U& x0,
                                          float d0, float* yp, bool doStore)
{
    unsigned long long dp = pack2(d0, d0);
    float a[4];
#pragma unroll
    for (int i = 0; i < 4; i++) {
        unsigned long long xp = pack2(x0.s[i], x0.s[i]);
        s[i][0] = ffma2(s[i][0], dp, fmul2(xp, bn.u[0]));
        s[i][1] = ffma2(s[i][1], dp, fmul2(xp, bn.u[1]));
        unsigned long long m = fmul2(s[i][0], cn.u[0]);
        m = ffma2(s[i][1], cn.u[1], m);
        float lo, hi;
        unpack2(m, lo, hi);
        a[i] = lo + hi;
    }
    int lane = threadIdx.x & 31;
    a[0] += __shfl_xor_sync(0xffffffffu, a[0], 16);
    a[1] += __shfl_xor_sync(0xffffffffu, a[1], 16);
    a[2] += __shfl_xor_sync(0xffffffffu, a[2], 16);
    a[3] += __shfl_xor_sync(0xffffffffu, a[3], 16);
    float b0 = (lane & 16) ? a[2] : a[0];
    float b1 = (lane & 16) ? a[3] : a[1];
    b0 += __shfl_xor_sync(0xffffffffu, b0, 8);
    b1 += __shfl_xor_sync(0xffffffffu, b1, 8);
    float c0 = (lane & 8) ? b1 : b0;
    c0 += __shfl_xor_sync(0xffffffffu, c0, 4);
    c0 += __shfl_xor_sync(0xffffffffu, c0, 2);
    c0 += __shfl_xor_sync(0xffffffffu, c0, 1);
    if (doStore) *yp = c0;
}

// ---------------- phase 1: partial scans per segment (4 p per warp) ----------------
__global__ __launch_bounds__(128)
void scan_partial()
{
    int bid  = blockIdx.x;            // 1024 = b(8) h(4) seg(8) pb(4)
    int b    = bid >> 7;
    int h    = (bid >> 5) & 3;
    int seg  = (bid >> 2) & 7;
    int pb   = bid & 3;
    int widx = threadIdx.x >> 5;
    int lane = threadIdx.x & 31;
    int p    = pb * 16 + widx * 4;
    int t0   = seg * QSEG;

    const float* dAp = g_dA + ((size_t)b * Tseq + t0) * NHC + h;
    const F4U*   Xp  = (const F4U*)(g_dtx + ((size_t)b * Tseq + t0) * EXPC + h * HDC + p);
    const F4U*   Bp  = (const F4U*)(g_xbc + ((size_t)b * Tseq + t0) * 512 + 256) + lane;
    const F4U*   Cp  = (const F4U*)(g_xbc + ((size_t)b * Tseq + t0) * 512 + 384) + lane;
    int plocal = ((lane >> 4) << 1) | ((lane >> 3) & 1);
    float* yp = g_y + ((size_t)b * Tseq + t0) * EXPC + h * HDC + p + plocal;
    bool doStore = ((lane & 7) == 0);

    unsigned long long s[4][2];
#pragma unroll
    for (int i = 0; i < 4; i++) { s[i][0] = 0ull; s[i][1] = 0ull; }

    F4U bv, cv, xx;
    bv = *Bp; cv = *Cp; xx = *Xp;
    float da = *dAp;
    for (int t = 0; t < QSEG - 1; t++) {
        Bp += 128; Cp += 128; Xp += 64; dAp += 4;
        F4U bn = bv, cn = cv, x0 = xx;
        float d0 = da;
        bv = *Bp; cv = *Cp; xx = *Xp; da = *dAp;
        scan_step(s, bn, cn, x0, d0, yp, doStore);
        yp += EXPC;
    }
    scan_step(s, bv, cv, xx, da, yp, doStore);

    int bh = b * 4 + h;
    size_t sb = ((size_t)bh * SEGS + seg) * 64 + p;
#pragma unroll
    for (int i = 0; i < 4; i++) {
        F4U sv;
        sv.u[0] = s[i][0]; sv.u[1] = s[i][1];
        ((float4*)(g_spart + (sb + i) * 128))[lane] = sv.f;
    }
}

// ---------------- phase 2: carry initial states across segments ----------------
__global__ void carry_kernel()
{
    int bh = blockIdx.x;       // 32 blocks
    int tid = threadIdx.x;     // 256
    __shared__ float Ps[SEGS];
    if (tid < SEGS) Ps[tid] = g_e[(size_t)bh * Tseq + (size_t)(tid + 1) * QSEG - 1];
    __syncthreads();
    for (int k = 0; k < 32; k++) {
        int idx = tid + k * 256;  // p*128+n
        float sini = 0.f;
#pragma unroll
        for (int s = 1; s < SEGS; s++) {
            sini = g_spart[((size_t)bh * SEGS + (s - 1)) * 8192 + idx] + sini * Ps[s - 1];
            g_sinit[((size_t)bh * SEGS + s) * 8192 + idx] = sini;
        }
    }
}

// ---------------- phase 3: y[t,p] += e_t * (C_t . S_init) ----------------
#define BK 16
__global__ __launch_bounds__(256)
void corr_kernel()
{
    int mt  = blockIdx.x;            // 0..5
    int seg = blockIdx.y + 1;        // 1..7
    int bh  = blockIdx.z;            // 0..31
    int b = bh >> 2, h = bh & 3;
    int t0 = seg * QSEG + mt * 128;
    if (g_e[(size_t)bh * Tseq + t0] == 0.f) return;

    __shared__ __align__(16) float Cs[BK][132];
    __shared__ __align__(16) float Ss[BK][68];
    const int tid = threadIdx.x;
    const int tx = tid & 15;
    const int ty = tid >> 4;
    const int lr = tid >> 2;
    const int lc = (tid & 3) << 2;

    const float* Abase = g_xbc + ((size_t)(b * Tseq + t0)) * 512 + 384;
    const float* Sbase = g_sinit + ((size_t)bh * SEGS + seg) * 8192;
    float acc[8][4];
#pragma unroll
    for (int i = 0; i < 8; i++)
#pragma unroll
        for (int j = 0; j < 4; j++) acc[i][j] = 0.f;

    const int mlim = QSEG - mt * 128;
    for (int k0 = 0; k0 < 128; k0 += BK) {
        float4 va = (lr < mlim) ? *(const float4*)(Abase + (size_t)lr * 512 + k0 + lc)
                                : make_float4(0.f, 0.f, 0.f, 0.f);
        float4 vb = (lr + 64 < mlim) ? *(const float4*)(Abase + (size_t)(lr + 64) * 512 + k0 + lc)
                                     : make_float4(0.f, 0.f, 0.f, 0.f);
        float4 vs = *(const float4*)(Sbase + (size_t)lr * 128 + k0 + lc);
        __syncthreads();
        Cs[lc + 0][lr] = va.x; Cs[lc + 1][lr] = va.y; Cs[lc + 2][lr] = va.z; Cs[lc + 3][lr] = va.w;
        Cs[lc + 0][lr + 64] = vb.x; Cs[lc + 1][lr + 64] = vb.y;
        Cs[lc + 2][lr + 64] = vb.z; Cs[lc + 3][lr + 64] = vb.w;
        Ss[lc + 0][lr] = vs.x; Ss[lc + 1][lr] = vs.y; Ss[lc + 2][lr] = vs.z; Ss[lc + 3][lr] = vs.w;
        __syncthreads();
#pragma unroll
        for (int kk = 0; kk < BK; kk++) {
            float4 a0 = *(const float4*)&Cs[kk][ty * 8];
            float4 a1 = *(const float4*)&Cs[kk][ty * 8 + 4];
            float4 bq = *(const float4*)&Ss[kk][tx * 4];
            float av[8] = {a0.x, a0.y, a0.z, a0.w, a1.x, a1.y, a1.z, a1.w};
            float bw[4] = {bq.x, bq.y, bq.z, bq.w};
#pragma unroll
            for (int i = 0; i < 8; i++)
#pragma unroll
                for (int j = 0; j < 4; j++)
                    acc[i][j] = fmaf(av[i], bw[j], acc[i][j]);
        }
    }
#pragma unroll
    for (int i = 0; i < 8; i++) {
        int mrow = ty * 8 + i;
        if (mrow >= mlim) continue;
        int tg = t0 + mrow;
        float e = g_e[(size_t)bh * Tseq + tg];
        float* yd = g_y + ((size_t)(b * Tseq + tg)) * EXPC + h * 64 + tx * 4;
        float4 old = *(float4*)yd;
        old.x += e * acc[i][0];
        old.y += e * acc[i][1];
        old.z += e * acc[i][2];
        old.w += e * acc[i][3];
        *(float4*)yd = old;
    }
}

// ---------------- gate_norm: 4 rows/block, 2 warps/row, float4 ----------------
__global__ __launch_bounds__(256)
void gate_norm(const float* __restrict__ Dp, const float* __restrict__ gnw)
{
    int tid = threadIdx.x;
    int rl  = tid >> 6;                 // row within block 0..3
    int row = blockIdx.x * 4 + rl;
    int ci  = tid & 63;                 // float4 index within row
    int c   = ci * 4;
    float4 xh = *(const float4*)(g_xbc + (size_t)row * 512 + c);
    float4 y4 = *(const float4*)(g_y + (size_t)row * EXPC + c);
    float4 g4 = *(const float4*)(g_proj + (size_t)row * PROJW + c);
    float Dv = Dp[c >> 6];
    float4 v;
    v.x = (y4.x + Dv * xh.x) * (g4.x / (1.f + expf(-g4.x)));
    v.y = (y4.y + Dv * xh.y) * (g4.y / (1.f + expf(-g4.y)));
    v.z = (y4.z + Dv * xh.z) * (g4.z / (1.f + expf(-g4.z)));
    v.w = (y4.w + Dv * xh.w) * (g4.w / (1.f + expf(-g4.w)));
    float s = v.x * v.x + v.y * v.y + v.z * v.z + v.w * v.w;
#pragma unroll
    for (int o = 16; o > 0; o >>= 1) s += __shfl_xor_sync(0xffffffffu, s, o);
    __shared__ float ws[8];
    if ((tid & 31) == 0) ws[tid >> 5] = s;
    __syncthreads();
    float tot = ws[rl * 2] + ws[rl * 2 + 1];
    float sc = rsqrtf(tot * (1.f / EXPC) + 1e-5f);
    float4 gn = *(const float4*)(gnw + c);
    float4 o4 = make_float4(v.x * sc * gn.x, v.y * sc * gn.y,
                            v.z * sc * gn.z, v.w * sc * gn.w);
    store_split4(g_ahi + (size_t)row * EXPC + c, g_alo + (size_t)row * EXPC + c, o4);
}

// ---------------- combine 4 directional outputs -> bf16 split ----------------
__global__ void combine_kernel()
{
    int bl = blockIdx.x;
    int b = bl / Lseq, l = bl % Lseq;
    int hg = l / WGc, wg = l % WGc;
    int j = wg * HGc + hg;
    int tid = threadIdx.x;
    size_t base = (size_t)b * Tseq;
    float v = g_hn[(base + l) * DMc + tid]
            + g_hn[(base + Lseq + j) * DMc + tid]
            + g_hn[(base + 2 * Lseq + (Lseq - 1 - l)) * DMc + tid]
            + g_hn[(base + 3 * Lseq + (Lseq - 1 - j)) * DMc + tid];
    __nv_bfloat16 hi = __float2bfloat16(v);
    g_ahi[(size_t)bl * DMc + tid] = hi;
    g_alo[(size_t)bl * DMc + tid] = __float2bfloat16(v - __bfloat162float(hi));
}

// ---------------- unpatchify to (B,CIN,340,720) ----------------
__global__ void unpatch(float* __restrict__ out)
{
    int idx = blockIdx.x * blockDim.x + threadIdx.x;
    if (idx >= NPATCH * 480) return;
    int xc = idx % 720;
    int t1 = idx / 720;
    int y  = t1 % 340;
    int t2 = t1 / 340;
    int c  = t2 % 3;
    int b  = t2 / 3;
    int hg = y / PHc,  i  = y % PHc;
    int wg = xc / PWc, jj = xc % PWc;
    int l  = hg * WGc + wg;
    out[idx] = g_proj[((size_t)(b * Lseq + l)) * 480 + i * 24 + jj * 3 + c];
}

// ---------------- host orchestration ----------------
static void* sym_addr(const void* sym)
{
    void* p = nullptr;
    cudaGetSymbolAddress(&p, sym);
    return p;
}

extern "C" void kernel_launch(void* const* d_in, const int* in_sizes, int n_in,
                              void* d_out, int out_size)
{
    (void)in_sizes; (void)n_in; (void)out_size;
    const float* x       = (const float*)d_in[0];
    const float* W_pe    = (const float*)d_in[1];
    const float* b_pe    = (const float*)d_in[2];
    const float* norm_w  = (const float*)d_in[3];
    const float* in_w    = (const float*)d_in[4];
    const float* in_b    = (const float*)d_in[5];
    const float* conv_w  = (const float*)d_in[6];
    const float* conv_b  = (const float*)d_in[7];
    const float* dt_bias = (const float*)d_in[8];
    const float* A_log   = (const float*)d_in[9];
    const float* Dp      = (const float*)d_in[10];
    const float* gn_w    = (const float*)d_in[11];
    const float* out_w   = (const float*)d_in[12];
    const float* out_b   = (const float*)d_in[13];
    const float* normf_w = (const float*)d_in[14];
    const float* r1_w    = (const float*)d_in[15];
    const float* r1_b    = (const float*)d_in[16];
    const float* r2_w    = (const float*)d_in[17];
    const float* r2_b    = (const float*)d_in[18];
    float* out = (float*)d_out;

    float* hbuf = (float*)sym_addr(g_h);
    float* hn   = (float*)sym_addr(g_hn);
    float* proj = (float*)sym_addr(g_proj);
    __nv_bfloat16* ahi  = (__nv_bfloat16*)sym_addr(g_ahi);
    __nv_bfloat16* alo  = (__nv_bfloat16*)sym_addr(g_alo);
    __nv_bfloat16* whi  = (__nv_bfloat16*)sym_addr(g_whi);
    __nv_bfloat16* wlo  = (__nv_bfloat16*)sym_addr(g_wlo);
    __nv_bfloat16* wihi = (__nv_bfloat16*)sym_addr(g_wihi);
    __nv_bfloat16* wilo = (__nv_bfloat16*)sym_addr(g_wilo);
    __nv_bfloat16* wohi = (__nv_bfloat16*)sym_addr(g_wohi);
    __nv_bfloat16* wolo = (__nv_bfloat16*)sym_addr(g_wolo);
    __nv_bfloat16* r1hi = (__nv_bfloat16*)sym_addr(g_r1hi);
    __nv_bfloat16* r1lo = (__nv_bfloat16*)sym_addr(g_r1lo);
    __nv_bfloat16* r2hi = (__nv_bfloat16*)sym_addr(g_r2hi);
    __nv_bfloat16* r2lo = (__nv_bfloat16*)sym_addr(g_r2lo);
    __nv_bfloat16* bhi  = (__nv_bfloat16*)sym_addr(g_bhi);
    __nv_bfloat16* blo  = (__nv_bfloat16*)sym_addr(g_blo);
    __nv_bfloat16* phi  = (__nv_bfloat16*)sym_addr(g_pathi);
    __nv_bfloat16* plo  = (__nv_bfloat16*)sym_addr(g_patlo);

    static int smem_set = 0;
    if (!smem_set) {
        cudaFuncSetAttribute(mma_gemm, cudaFuncAttributeMaxDynamicSharedMemorySize, MMA_SMEM);
        smem_set = 1;
    }

    const int MTL = (NPATCH + 127) / 128;  // 96
    const int MT  = (BT + 127) / 128;      // 383

    // ---- upfront weight conversions (all layers) ----
    wsplit<<<(4 * 772 * DMc + 255) / 256, 256>>>(in_w, wihi, wilo, 4 * 772 * DMc);
    wsplit<<<(4 * DMc * EXPC + 255) / 256, 256>>>(out_w, wohi, wolo, 4 * DMc * EXPC);
    wsplit<<<(DMc * DMc + 255) / 256, 256>>>(r1_w, r1hi, r1lo, DMc * DMc);
    wsplit<<<(480 * DMc + 255) / 256, 256>>>(r2_w, r2hi, r2lo, 480 * DMc);
    wconv_pad<<<(128 * 512 + 255) / 256, 256>>>(W_pe, 128, 480, 512);

    // patch embed (padded K=512) with fused 4-direction scatter into g_h
    patch_gather<<<(NPATCH * 512 + 255) / 256, 256>>>(x);
    mma_gemm<<<dim3(1, MTL), 256, MMA_SMEM>>>(phi, plo, whi, wlo, b_pe, nullptr,
                                              hbuf, NPATCH, 512, DMc, DMc, 2);

    for (int l = 0; l < 4; l++) {
        const float* iw = in_w + (size_t)l * 772 * DMc;
        const float* ib = in_b + (size_t)l * 772;
        // rmsnorm + fused dt head (warp-per-row)
        rmsnorm128<<<BT / 8, 256>>>(hbuf, norm_w + l * DMc, nullptr, 1,
                                    iw + 768 * DMc, ib, dt_bias + l * NHC, A_log + l * NHC);
        // e_kernel depends only on dA -> run before the big GEMM (tail hides in ramp)
        e_kernel<<<32, 256>>>();
        mma_gemm<<<dim3(6, MT), 256, MMA_SMEM>>>(ahi, alo,
                                                 wihi + (size_t)l * 772 * DMc,
                                                 wilo + (size_t)l * 772 * DMc,
                                                 ib, nullptr,
                                                 proj, BT, DMc, PROJW, PROJW, 0);
        conv_silu<<<((BT / 4) * 128 + 255) / 256, 256>>>(conv_w + l * 512 * 4,
                                                         conv_b + l * 512);
        scan_partial<<<1024, 128>>>();
        carry_kernel<<<32, 256>>>();
        corr_kernel<<<dim3(6, SEGS - 1, 32), 256>>>();
        gate_norm<<<BT / 4, 256>>>(Dp + l * NHC, gn_w + l * EXPC);
        mma_gemm<<<dim3(1, MT), 256, MMA_SMEM>>>(ahi, alo,
                                                 wohi + (size_t)l * DMc * EXPC,
                                                 wolo + (size_t)l * DMc * EXPC,
                                                 out_b + l * DMc, hbuf,
                                                 hbuf, BT, EXPC, DMc, DMc, 0);
    }

    rmsnorm128<<<BT / 8, 256>>>(hbuf, normf_w, hn, 0, nullptr, nullptr, nullptr, nullptr);
    combine_kernel<<<NPATCH, 128>>>();
    // r1: gelu, emits bf16 split into g_bhi/g_blo
    mma_gemm<<<dim3(1, MTL), 256, MMA_SMEM>>>(ahi, alo, r1hi, r1lo, r1_b, nullptr,
                                              proj, NPATCH, DMc, DMc, DMc, 1);
    // r2: 480 outputs into g_proj, then coalesced unpatchify
    mma_gemm<<<dim3(4, MTL), 256, MMA_SMEM>>>(bhi, blo, r2hi, r2lo, r2_b, nullptr,
                                              proj, NPATCH, DMc, 480, 480, 0);
    unpatch<<<(NPATCH * 480 + 255) / 256, 256>>>(out);
}

// round 15
// speedup vs baseline: 1.1062x; 1.1062x over previous
#include <cuda_runtime.h>
#include <cuda_bf16.h>
#include <math.h>
#include <stdint.h>

// ---------------- problem constants ----------------
#define BATCH  8
#define HGc    17
#define WGc    90
#define Lseq   1530            // HG*WG
#define Tseq   6120            // 4*L
#define BT     48960           // BATCH*Tseq
#define DMc    128
#define EXPC   256
#define NHC    4
#define HDC    64
#define PHc    20
#define PWc    8
#define CINc   3
#define NPATCH 12240           // BATCH*Lseq
#define PROJW  768             // gate(256)+xBC(512); dt separate
#define SEGS   8
#define QSEG   765             // Tseq / SEGS

// ---------------- device scratch (static, no allocs) ----------------
__device__ float g_h      [(size_t)BT * DMc];
__device__ float g_hn     [(size_t)BT * DMc];
__device__ float g_proj   [(size_t)BT * PROJW];
__device__ float g_xbc    [(size_t)BT * 512];
__device__ float g_dt     [(size_t)BT * NHC];
__device__ float g_dA     [(size_t)BT * NHC];
__device__ float g_dtx    [(size_t)BT * EXPC];
__device__ float g_y      [(size_t)BT * EXPC];
__device__ float g_e      [(size_t)32 * Tseq];                 // cumprod dA per (b,h)
__device__ float g_spart  [(size_t)32 * SEGS * 64 * 128];      // segment-final partial states
__device__ float g_sinit  [(size_t)32 * SEGS * 64 * 128];      // segment initial states
// bf16 split operand buffers for tensor-core GEMMs
__device__ __nv_bfloat16 g_ahi[(size_t)BT * 256];
__device__ __nv_bfloat16 g_alo[(size_t)BT * 256];
__device__ __nv_bfloat16 g_whi[(size_t)768 * 256];      // patch-embed weight
__device__ __nv_bfloat16 g_wlo[(size_t)768 * 256];
__device__ __nv_bfloat16 g_wihi[(size_t)4 * 772 * DMc]; // in_proj weights (all layers)
__device__ __nv_bfloat16 g_wilo[(size_t)4 * 772 * DMc];
__device__ __nv_bfloat16 g_wohi[(size_t)4 * DMc * EXPC];// out_proj weights (all layers)
__device__ __nv_bfloat16 g_wolo[(size_t)4 * DMc * EXPC];
__device__ __nv_bfloat16 g_r1hi[DMc * DMc];
__device__ __nv_bfloat16 g_r1lo[DMc * DMc];
__device__ __nv_bfloat16 g_r2hi[480 * DMc];
__device__ __nv_bfloat16 g_r2lo[480 * DMc];
__device__ __nv_bfloat16 g_bhi[(size_t)NPATCH * DMc];
__device__ __nv_bfloat16 g_blo[(size_t)NPATCH * DMc];
__device__ __nv_bfloat16 g_pathi[(size_t)NPATCH * 512];
__device__ __nv_bfloat16 g_patlo[(size_t)NPATCH * 512];

__device__ __forceinline__ uint32_t smem_u32(const void* p)
{
    uint32_t a;
    asm("{ .reg .u64 t; cvta.to.shared.u64 t, %1; cvt.u32.u64 %0, t; }"
        : "=r"(a) : "l"(p));
    return a;
}

__device__ __forceinline__ void ldmx4(uint32_t& r0, uint32_t& r1, uint32_t& r2,
                                      uint32_t& r3, uint32_t addr)
{
    asm volatile("ldmatrix.sync.aligned.m8n8.x4.shared.b16 {%0,%1,%2,%3}, [%4];"
                 : "=r"(r0), "=r"(r1), "=r"(r2), "=r"(r3) : "r"(addr));
}

__device__ __forceinline__ void mma_bf16(float* d, const uint32_t* a, const uint32_t* b)
{
    asm volatile(
        "mma.sync.aligned.m16n8k16.row.col.f32.bf16.bf16.f32 "
        "{%0,%1,%2,%3}, {%4,%5,%6,%7}, {%8,%9}, {%0,%1,%2,%3};"
        : "+f"(d[0]), "+f"(d[1]), "+f"(d[2]), "+f"(d[3])
        : "r"(a[0]), "r"(a[1]), "r"(a[2]), "r"(a[3]), "r"(b[0]), "r"(b[1]));
}

// ---------------- f32x2 helpers ----------------
union F4U { float4 f; unsigned long long u[2]; float s[4]; };

__device__ __forceinline__ unsigned long long ffma2(unsigned long long a,
                                                    unsigned long long b,
                                                    unsigned long long c)
{
    unsigned long long d;
    asm("fma.rn.f32x2 %0, %1, %2, %3;" : "=l"(d) : "l"(a), "l"(b), "l"(c));
    return d;
}

__device__ __forceinline__ unsigned long long fmul2(unsigned long long a,
                                                    unsigned long long b)
{
    unsigned long long d;
    asm("mul.rn.f32x2 %0, %1, %2;" : "=l"(d) : "l"(a), "l"(b));
    return d;
}

__device__ __forceinline__ unsigned long long pack2(float lo, float hi)
{
    unsigned long long d;
    asm("mov.b64 %0, {%1, %2};" : "=l"(d) : "f"(lo), "f"(hi));
    return d;
}

__device__ __forceinline__ void unpack2(unsigned long long v, float& lo, float& hi)
{
    asm("mov.b64 {%0, %1}, %2;" : "=f"(lo), "=f"(hi) : "l"(v));
}

// ---------------- pack 4 floats -> 4 bf16 hi + 4 bf16 lo stores ----------------
__device__ __forceinline__ void store_split4(__nv_bfloat16* hi_dst, __nv_bfloat16* lo_dst,
                                             float4 v)
{
    __nv_bfloat16 hh[4], ll[4];
    float vs[4] = {v.x, v.y, v.z, v.w};
#pragma unroll
    for (int i = 0; i < 4; i++) {
        hh[i] = __float2bfloat16(vs[i]);
        ll[i] = __float2bfloat16(vs[i] - __bfloat162float(hh[i]));
    }
    *(uint2*)hi_dst = *(uint2*)hh;
    *(uint2*)lo_dst = *(uint2*)ll;
}

// ---------------- bf16-split tensor-core GEMM (mma.sync) ----------------
// mode 0: C = A@W^T + bias (+resid)
// mode 1: gelu(A@W^T + bias) -> bf16 hi/lo split into g_bhi/g_blo (C unused)
// mode 2: A@W^T + bias scattered into 4 directional rows of C (=g_h)
#define MLDS 72   // smem row pitch in bf16 (144 bytes)

__device__ __forceinline__ void epi_store(int mode, float* C, int ldc,
                                          const float* resid, int row, int col,
                                          float vx, float vy)
{
    if (mode == 1) {
        __nv_bfloat16 hx = __float2bfloat16(vx);
        __nv_bfloat16 hy = __float2bfloat16(vy);
        g_bhi[(size_t)row * ldc + col] = hx;
        g_bhi[(size_t)row * ldc + col + 1] = hy;
        g_blo[(size_t)row * ldc + col] = __float2bfloat16(vx - __bfloat162float(hx));
        g_blo[(size_t)row * ldc + col + 1] = __float2bfloat16(vy - __bfloat162float(hy));
    } else if (mode == 2) {
        int b = row / Lseq, l = row % Lseq;
        int hg = l / WGc, wg = l % WGc;
        int j = wg * HGc + hg;
        size_t base = (size_t)b * Tseq;
        float2 v = make_float2(vx, vy);
        *(float2*)(C + (base + l) * DMc + col) = v;
        *(float2*)(C + (base + Lseq + j) * DMc + col) = v;
        *(float2*)(C + (base + 2 * Lseq + (Lseq - 1 - l)) * DMc + col) = v;
        *(float2*)(C + (base + 3 * Lseq + (Lseq - 1 - j)) * DMc + col) = v;
    } else {
        if (resid) {
            vx += resid[(size_t)row * ldc + col];
            vy += resid[(size_t)row * ldc + col + 1];
        }
        *(float2*)(C + (size_t)row * ldc + col) = make_float2(vx, vy);
    }
}

__global__ __launch_bounds__(256)
void mma_gemm(const __nv_bfloat16* __restrict__ Ahi, const __nv_bfloat16* __restrict__ Alo,
              const __nv_bfloat16* __restrict__ Whi, const __nv_bfloat16* __restrict__ Wlo,
              const float* __restrict__ bias, const float* __restrict__ resid,
              float* __restrict__ C, int M, int Ktot, int N, int ldc, int mode)
{
    extern __shared__ __align__(16) __nv_bfloat16 sm[];
    __nv_bfloat16* sAh = sm;
    __nv_bfloat16* sAl = sAh + 128 * MLDS;
    __nv_bfloat16* sWh = sAl + 128 * MLDS;
    __nv_bfloat16* sWl = sWh + 128 * MLDS;
    const uint32_t bAh = smem_u32(sAh);
    const uint32_t bAl = smem_u32(sAl);
    const uint32_t bWh = smem_u32(sWh);
    const uint32_t bWl = smem_u32(sWl);

    const int tid  = threadIdx.x;
    const int wid  = tid >> 5;
    const int lane = tid & 31;
    const int m0 = blockIdx.y * 128;
    const int n0 = blockIdx.x * 128;
    const int wm = (wid >> 2) * 64;
    const int wn = (wid & 3) * 32;

    float acc[4][4][4];
#pragma unroll
    for (int i = 0; i < 4; i++)
#pragma unroll
        for (int j = 0; j < 4; j++)
#pragma unroll
            for (int q = 0; q < 4; q++) acc[i][j][q] = 0.f;

    const int lrow = tid >> 1;
    const int lcol = (tid & 1) * 32;
    const bool okA = (m0 + lrow) < M;
    const bool okW = (n0 + lrow) < N;
    const uint4 z16 = make_uint4(0u, 0u, 0u, 0u);
    const int lm_row = lane & 15;
    const int lm_col = (lane >> 4) * 8;

    for (int kc = 0; kc < Ktot; kc += 64) {
        if (kc) __syncthreads();
        const uint4* pAh = (const uint4*)(Ahi + (size_t)(m0 + lrow) * Ktot + kc + lcol);
        const uint4* pAl = (const uint4*)(Alo + (size_t)(m0 + lrow) * Ktot + kc + lcol);
        const uint4* pWh = (const uint4*)(Whi + (size_t)(n0 + lrow) * Ktot + kc + lcol);
        const uint4* pWl = (const uint4*)(Wlo + (size_t)(n0 + lrow) * Ktot + kc + lcol);
        uint4* dAh = (uint4*)(sAh + lrow * MLDS + lcol);
        uint4* dAl = (uint4*)(sAl + lrow * MLDS + lcol);
        uint4* dWh = (uint4*)(sWh + lrow * MLDS + lcol);
        uint4* dWl = (uint4*)(sWl + lrow * MLDS + lcol);
#pragma unroll
        for (int q = 0; q < 4; q++) {
            dAh[q] = okA ? pAh[q] : z16;
            dAl[q] = okA ? pAl[q] : z16;
            dWh[q] = okW ? pWh[q] : z16;
            dWl[q] = okW ? pWl[q] : z16;
        }
        __syncthreads();

#pragma unroll
        for (int ks = 0; ks < 4; ks++) {
            const int k0 = ks * 16;
            uint32_t bh[4][2], bl[4][2];
#pragma unroll
            for (int pr = 0; pr < 2; pr++) {
                uint32_t off = (uint32_t)(((wn + pr * 16 + lm_row) * MLDS + k0 + lm_col) * 2);
                uint32_t r0, r1, r2, r3;
                ldmx4(r0, r1, r2, r3, bWh + off);
                bh[pr * 2][0] = r0; bh[pr * 2 + 1][0] = r1;
                bh[pr * 2][1] = r2; bh[pr * 2 + 1][1] = r3;
                ldmx4(r0, r1, r2, r3, bWl + off);
                bl[pr * 2][0] = r0; bl[pr * 2 + 1][0] = r1;
                bl[pr * 2][1] = r2; bl[pr * 2 + 1][1] = r3;
            }
#pragma unroll
            for (int mt = 0; mt < 4; mt++) {
                uint32_t off = (uint32_t)(((wm + mt * 16 + lm_row) * MLDS + k0 + lm_col) * 2);
                uint32_t ah[4], al[4];
                ldmx4(ah[0], ah[1], ah[2], ah[3], bAh + off);
                ldmx4(al[0], al[1], al[2], al[3], bAl + off);
#pragma unroll
                for (int nt = 0; nt < 4; nt++) {
                    mma_bf16(acc[mt][nt], ah, bh[nt]);
                    mma_bf16(acc[mt][nt], ah, bl[nt]);
                    mma_bf16(acc[mt][nt], al, bh[nt]);
                }
            }
        }
    }

    const int gid = lane >> 2;
    const int tig = lane & 3;
#pragma unroll
    for (int mt = 0; mt < 4; mt++) {
        int row0 = m0 + wm + mt * 16 + gid;
        int row1 = row0 + 8;
#pragma unroll
        for (int nt = 0; nt < 4; nt++) {
            int col = n0 + wn + nt * 8 + tig * 2;
            if (col >= N) continue;
            float bx = bias[col];
            float by = bias[col + 1];
            if (row0 < M) {
                float vx = acc[mt][nt][0] + bx, vy = acc[mt][nt][1] + by;
                if (mode == 1) {
                    vx = 0.5f * vx * (1.f + erff(vx * 0.7071067811865475f));
                    vy = 0.5f * vy * (1.f + erff(vy * 0.7071067811865475f));
                }
                epi_store(mode, C, ldc, resid, row0, col, vx, vy);
            }
            if (row1 < M) {
                float vx = acc[mt][nt][2] + bx, vy = acc[mt][nt][3] + by;
                if (mode == 1) {
                    vx = 0.5f * vx * (1.f + erff(vx * 0.7071067811865475f));
                    vy = 0.5f * vy * (1.f + erff(vy * 0.7071067811865475f));
                }
                epi_store(mode, C, ldc, resid, row1, col, vx, vy);
            }
        }
    }
}
#define MMA_SMEM (4 * 128 * MLDS * 2)

// ---------------- weight fp32 -> bf16 hi/lo split (fused: in_w all layers + out_w) ----
__global__ void wsplit2(const float* __restrict__ w1, __nv_bfloat16* __restrict__ h1,
                        __nv_bfloat16* __restrict__ l1, int n1,
                        const float* __restrict__ w2, __nv_bfloat16* __restrict__ h2,
                        __nv_bfloat16* __restrict__ l2, int n2)
{
    int idx = blockIdx.x * blockDim.x + threadIdx.x;
    if (idx < n1) {
        float v = w1[idx];
        __nv_bfloat16 h = __float2bfloat16(v);
        h1[idx] = h;
        l1[idx] = __float2bfloat16(v - __bfloat162float(h));
    } else if (idx < n1 + n2) {
        int k = idx - n1;
        float v = w2[k];
        __nv_bfloat16 h = __float2bfloat16(v);
        h2[k] = h;
        l2[k] = __float2bfloat16(v - __bfloat162float(h));
    }
}

__global__ void wconv_pad(const float* __restrict__ w, int N, int Ksrc, int Kdst)
{
    int idx = blockIdx.x * blockDim.x + threadIdx.x;
    if (idx >= N * Kdst) return;
    int k = idx % Kdst, n = idx / Kdst;
    float v = (k < Ksrc) ? w[n * Ksrc + k] : 0.f;
    __nv_bfloat16 hi = __float2bfloat16(v);
    g_whi[idx] = hi;
    g_wlo[idx] = __float2bfloat16(v - __bfloat162float(hi));
}

// ---------------- patch gather (bf16 split, K padded 480->512) ----------------
__global__ void patch_gather(const float* __restrict__ x)
{
    int idx = blockIdx.x * blockDim.x + threadIdx.x;
    if (idx >= NPATCH * 512) return;
    int q  = idx & 511;
    int bl = idx >> 9;
    float v = 0.f;
    if (q < 480) {
        int c = q / 160, rr = q % 160;
        int i = rr / PWc, jj = rr % PWc;
        int b = bl / Lseq, l = bl % Lseq;
        int hg = l / WGc, wg = l % WGc;
        v = x[(((size_t)(b * CINc + c) * 340) + hg * PHc + i) * 720 + wg * PWc + jj];
    }
    __nv_bfloat16 hi = __float2bfloat16(v);
    g_pathi[idx] = hi;
    g_patlo[idx] = __float2bfloat16(v - __bfloat162float(hi));
}

// ---------------- rmsnorm: warp per row, float4 per lane, fused dt head ----------------
__global__ __launch_bounds__(256)
void rmsnorm128(const float* __restrict__ X, const float* __restrict__ w,
                float* __restrict__ Y, int emit_bf16,
                const float* __restrict__ wdt, const float* __restrict__ inb,
                const float* __restrict__ dtb, const float* __restrict__ alog)
{
    int wid  = threadIdx.x >> 5;
    int lane = threadIdx.x & 31;
    int row  = blockIdx.x * 8 + wid;
    float4 vx = *(const float4*)(X + (size_t)row * DMc + lane * 4);
    float s = vx.x * vx.x + vx.y * vx.y + vx.z * vx.z + vx.w * vx.w;
#pragma unroll
    for (int o = 16; o > 0; o >>= 1) s += __shfl_xor_sync(0xffffffffu, s, o);
    float sc = rsqrtf(s * (1.f / DMc) + 1e-5f);
    float4 wv = *(const float4*)(w + lane * 4);
    float4 o4 = make_float4(vx.x * sc * wv.x, vx.y * sc * wv.y,
                            vx.z * sc * wv.z, vx.w * sc * wv.w);
    if (Y) *(float4*)(Y + (size_t)row * DMc + lane * 4) = o4;
    if (emit_bf16)
        store_split4(g_ahi + (size_t)row * DMc + lane * 4,
                     g_alo + (size_t)row * DMc + lane * 4, o4);
    if (wdt) {
        float dts[4];
#pragma unroll
        for (int h = 0; h < 4; h++) {
            float4 q = *(const float4*)(wdt + h * DMc + lane * 4);
            float t = o4.x * q.x + o4.y * q.y + o4.z * q.z + o4.w * q.w;
#pragma unroll
            for (int o = 16; o > 0; o >>= 1) t += __shfl_xor_sync(0xffffffffu, t, o);
            dts[h] = t;
        }
        if (lane == 0) {
#pragma unroll
            for (int h = 0; h < 4; h++) {
                float xv = dts[h] + inb[768 + h] + dtb[h];
                float sp = (xv > 20.f) ? xv : log1pf(expf(xv));
                g_dt[row * 4 + h] = sp;
                g_dA[row * 4 + h] = expf(-expf(alog[h]) * sp);
            }
        }
    }
}

// ---------------- conv(K=4)+silu, time-tiled x4, fused dtx ----------------
__global__ void conv_silu(const float* __restrict__ cw, const float* __restrict__ cb)
{
    int idx = blockIdx.x * blockDim.x + threadIdx.x;   // (BT/4)*128
    if (idx >= (BT / 4) * 128) return;
    int c4 = idx & 127;
    int q4 = idx >> 7;
    int tq = q4 % (Tseq / 4), b = q4 / (Tseq / 4);
    int t0 = tq * 4;
    int c = c4 * 4;
    float4 bias = *(const float4*)(cb + c);
    float4 w0 = *(const float4*)(cw + (c + 0) * 4);
    float4 w1 = *(const float4*)(cw + (c + 1) * 4);
    float4 w2 = *(const float4*)(cw + (c + 2) * 4);
    float4 w3 = *(const float4*)(cw + (c + 3) * 4);
    const float* base = g_proj + ((size_t)(b * Tseq + t0)) * PROJW + 256 + c;
    float4 in[7];
#pragma unroll
    for (int k = 0; k < 7; k++) {
        int tt = t0 + k - 3;
        in[k] = (tt >= 0) ? *(const float4*)(base + (ptrdiff_t)(k - 3) * PROJW)
                          : make_float4(0.f, 0.f, 0.f, 0.f);
    }
    size_t bt0 = (size_t)b * Tseq + t0;
#pragma unroll
    for (int q = 0; q < 4; q++) {
        float4 acc = bias;
#pragma unroll
        for (int k = 0; k < 4; k++) {
            float4 v = in[q + k];
            acc.x = fmaf(v.x, ((const float*)&w0)[k], acc.x);
            acc.y = fmaf(v.y, ((const float*)&w1)[k], acc.y);
            acc.z = fmaf(v.z, ((const float*)&w2)[k], acc.z);
            acc.w = fmaf(v.w, ((const float*)&w3)[k], acc.w);
        }
        float4 val;
        val.x = acc.x / (1.f + expf(-acc.x));
        val.y = acc.y / (1.f + expf(-acc.y));
        val.z = acc.z / (1.f + expf(-acc.z));
        val.w = acc.w / (1.f + expf(-acc.w));
        *(float4*)(g_xbc + (bt0 + q) * 512 + c) = val;
        if (c4 < 64) {
            float dtv = g_dt[(bt0 + q) * 4 + (c4 >> 4)];
            *(float4*)(g_dtx + (bt0 + q) * EXPC + c) =
                make_float4(val.x * dtv, val.y * dtv, val.z * dtv, val.w * dtv);
        }
    }
}

// ---------------- cumprod of dA within each segment ----------------
__global__ void e_kernel()
{
    int gw   = blockIdx.x * 8 + (threadIdx.x >> 5);   // 0..255 = bh(32) x seg(8)
    int lane = threadIdx.x & 31;
    int bh = gw >> 3, seg = gw & 7;
    int b = bh >> 2, h = bh & 3;
    size_t dbase = ((size_t)b * Tseq + seg * QSEG) * 4 + h;
    float v[24];
    float prod = 1.f;
#pragma unroll
    for (int i = 0; i < 24; i++) {
        int t = lane * 24 + i;
        float d = (t < QSEG) ? g_dA[dbase + (size_t)t * 4] : 1.f;
        prod *= d;
        v[i] = prod;
    }
    float inc = prod;
#pragma unroll
    for (int o = 1; o < 32; o <<= 1) {
        float q = __shfl_up_sync(0xffffffffu, inc, o);
        if (lane >= o) inc *= q;
    }
    float exs = __shfl_up_sync(0xffffffffu, inc, 1);
    if (lane == 0) exs = 1.f;
    size_t ebase = (size_t)bh * Tseq + seg * QSEG;
#pragma unroll
    for (int i = 0; i < 24; i++) {
        int t = lane * 24 + i;
        if (t < QSEG) g_e[ebase + t] = exs * v[i];
    }
}

// ---------------- scan step body (packed f32x2) ----------------
__device__ __forceinline__ void scan_step(unsigned long long s[4][2],
                                          const F4U& bn, const F4U& cn, const F4U& x0,
                                          float d0, float* yp, bool doStore)
{
    unsigned long long dp = pack2(d0, d0);
    float a[4];
#pragma unroll
    for (int i = 0; i < 4; i++) {
        unsigned long long xp = pack2(x0.s[i], x0.s[i]);
        s[i][0] = ffma2(s[i][0], dp, fmul2(xp, bn.u[0]));
        s[i][1] = ffma2(s[i][1], dp, fmul2(xp, bn.u[1]));
        unsigned long long m = fmul2(s[i][0], cn.u[0]);
        m = ffma2(s[i][1], cn.u[1], m);
        float lo, hi;
        unpack2(m, lo, hi);
        a[i] = lo + hi;
    }
    int lane = threadIdx.x & 31;
    a[0] += __shfl_xor_sync(0xffffffffu, a[0], 16);
    a[1] += __shfl_xor_sync(0xffffffffu, a[1], 16);
    a[2] += __shfl_xor_sync(0xffffffffu, a[2], 16);
    a[3] += __shfl_xor_sync(0xffffffffu, a[3], 16);
    float b0 = (lane & 16) ? a[2] : a[0];
    float b1 = (lane & 16) ? a[3] : a[1];
    b0 += __shfl_xor_sync(0xffffffffu, b0, 8);
    b1 += __shfl_xor_sync(0xffffffffu, b1, 8);
    float c0 = (lane & 8) ? b1 : b0;
    c0 += __shfl_xor_sync(0xffffffffu, c0, 4);
    c0 += __shfl_xor_sync(0xffffffffu, c0, 2);
    c0 += __shfl_xor_sync(0xffffffffu, c0, 1);
    if (doStore) *yp = c0;
}

// ---------------- phase 1: partial scans per segment (4 p per warp) ----------------
__global__ __launch_bounds__(128)
void scan_partial()
{
    int bid  = blockIdx.x;            // 1024 = b(8) h(4) seg(8) pb(4)
    int b    = bid >> 7;
    int h    = (bid >> 5) & 3;
    int seg  = (bid >> 2) & 7;
    int pb   = bid & 3;
    int widx = threadIdx.x >> 5;
    int lane = threadIdx.x & 31;
    int p    = pb * 16 + widx * 4;
    int t0   = seg * QSEG;

    const float* dAp = g_dA + ((size_t)b * Tseq + t0) * NHC + h;
    const F4U*   Xp  = (const F4U*)(g_dtx + ((size_t)b * Tseq + t0) * EXPC + h * HDC + p);
    const F4U*   Bp  = (const F4U*)(g_xbc + ((size_t)b * Tseq + t0) * 512 + 256) + lane;
    const F4U*   Cp  = (const F4U*)(g_xbc + ((size_t)b * Tseq + t0) * 512 + 384) + lane;
    int plocal = ((lane >> 4) << 1) | ((lane >> 3) & 1);
    float* yp = g_y + ((size_t)b * Tseq + t0) * EXPC + h * HDC + p + plocal;
    bool doStore = ((lane & 7) == 0);

    unsigned long long s[4][2];
#pragma unroll
    for (int i = 0; i < 4; i++) { s[i][0] = 0ull; s[i][1] = 0ull; }

    F4U bv, cv, xx;
    bv = *Bp; cv = *Cp; xx = *Xp;
    float da = *dAp;
    for (int t = 0; t < QSEG - 1; t++) {
        Bp += 128; Cp += 128; Xp += 64; dAp += 4;
        F4U bn = bv, cn = cv, x0 = xx;
        float d0 = da;
        bv = *Bp; cv = *Cp; xx = *Xp; da = *dAp;
        scan_step(s, bn, cn, x0, d0, yp, doStore);
        yp += EXPC;
    }
    scan_step(s, bv, cv, xx, da, yp, doStore);

    int bh = b * 4 + h;
    size_t sb = ((size_t)bh * SEGS + seg) * 64 + p;
#pragma unroll
    for (int i = 0; i < 4; i++) {
        F4U sv;
        sv.u[0] = s[i][0]; sv.u[1] = s[i][1];
        ((float4*)(g_spart + (sb + i) * 128))[lane] = sv.f;
    }
}

// ---------------- phase 2: carry initial states across segments ----------------
__global__ void carry_kernel()
{
    int bh = blockIdx.x;       // 32 blocks
    int tid = threadIdx.x;     // 256
    __shared__ float Ps[SEGS];
    if (tid < SEGS) Ps[tid] = g_e[(size_t)bh * Tseq + (size_t)(tid + 1) * QSEG - 1];
    __syncthreads();
    for (int k = 0; k < 32; k++) {
        int idx = tid + k * 256;  // p*128+n
        float sini = 0.f;
#pragma unroll
        for (int s = 1; s < SEGS; s++) {
            sini = g_spart[((size_t)bh * SEGS + (s - 1)) * 8192 + idx] + sini * Ps[s - 1];
            g_sinit[((size_t)bh * SEGS + s) * 8192 + idx] = sini;
        }
    }
}

// ---------------- phase 3: y[t,p] += e_t * (C_t . S_init) ----------------
#define BK 16
__global__ __launch_bounds__(256)
void corr_kernel()
{
    int mt  = blockIdx.x;            // 0..5
    int seg = blockIdx.y + 1;        // 1..7
    int bh  = blockIdx.z;            // 0..31
    int b = bh >> 2, h = bh & 3;
    int t0 = seg * QSEG + mt * 128;
    if (g_e[(size_t)bh * Tseq + t0] == 0.f) return;

    __shared__ __align__(16) float Cs[BK][132];
    __shared__ __align__(16) float Ss[BK][68];
    const int tid = threadIdx.x;
    const int tx = tid & 15;
    const int ty = tid >> 4;
    const int lr = tid >> 2;
    const int lc = (tid & 3) << 2;

    const float* Abase = g_xbc + ((size_t)(b * Tseq + t0)) * 512 + 384;
    const float* Sbase = g_sinit + ((size_t)bh * SEGS + seg) * 8192;
    float acc[8][4];
#pragma unroll
    for (int i = 0; i < 8; i++)
#pragma unroll
        for (int j = 0; j < 4; j++) acc[i][j] = 0.f;

    const int mlim = QSEG - mt * 128;
    for (int k0 = 0; k0 < 128; k0 += BK) {
        float4 va = (lr < mlim) ? *(const float4*)(Abase + (size_t)lr * 512 + k0 + lc)
                                : make_float4(0.f, 0.f, 0.f, 0.f);
        float4 vb = (lr + 64 < mlim) ? *(const float4*)(Abase + (size_t)(lr + 64) * 512 + k0 + lc)
                                     : make_float4(0.f, 0.f, 0.f, 0.f);
        float4 vs = *(const float4*)(Sbase + (size_t)lr * 128 + k0 + lc);
        __syncthreads();
        Cs[lc + 0][lr] = va.x; Cs[lc + 1][lr] = va.y; Cs[lc + 2][lr] = va.z; Cs[lc + 3][lr] = va.w;
        Cs[lc + 0][lr + 64] = vb.x; Cs[lc + 1][lr + 64] = vb.y;
        Cs[lc + 2][lr + 64] = vb.z; Cs[lc + 3][lr + 64] = vb.w;
        Ss[lc + 0][lr] = vs.x; Ss[lc + 1][lr] = vs.y; Ss[lc + 2][lr] = vs.z; Ss[lc + 3][lr] = vs.w;
        __syncthreads();
#pragma unroll
        for (int kk = 0; kk < BK; kk++) {
            float4 a0 = *(const float4*)&Cs[kk][ty * 8];
            float4 a1 = *(const float4*)&Cs[kk][ty * 8 + 4];
            float4 bq = *(const float4*)&Ss[kk][tx * 4];
            float av[8] = {a0.x, a0.y, a0.z, a0.w, a1.x, a1.y, a1.z, a1.w};
            float bw[4] = {bq.x, bq.y, bq.z, bq.w};
#pragma unroll
            for (int i = 0; i < 8; i++)
#pragma unroll
                for (int j = 0; j < 4; j++)
                    acc[i][j] = fmaf(av[i], bw[j], acc[i][j]);
        }
    }
#pragma unroll
    for (int i = 0; i < 8; i++) {
        int mrow = ty * 8 + i;
        if (mrow >= mlim) continue;
        int tg = t0 + mrow;
        float e = g_e[(size_t)bh * Tseq + tg];
        float* yd = g_y + ((size_t)(b * Tseq + tg)) * EXPC + h * 64 + tx * 4;
        float4 old = *(float4*)yd;
        old.x += e * acc[i][0];
        old.y += e * acc[i][1];
        old.z += e * acc[i][2];
        old.w += e * acc[i][3];
        *(float4*)yd = old;
    }
}

// ---------------- gate_norm: 4 rows/block, 2 warps/row, float4 ----------------
__global__ __launch_bounds__(256)
void gate_norm(const float* __restrict__ Dp, const float* __restrict__ gnw)
{
    int tid = threadIdx.x;
    int rl  = tid >> 6;                 // row within block 0..3
    int row = blockIdx.x * 4 + rl;
    int ci  = tid & 63;                 // float4 index within row
    int c   = ci * 4;
    float4 xh = *(const float4*)(g_xbc + (size_t)row * 512 + c);
    float4 y4 = *(const float4*)(g_y + (size_t)row * EXPC + c);
    float4 g4 = *(const float4*)(g_proj + (size_t)row * PROJW + c);
    float Dv = Dp[c >> 6];
    float4 v;
    v.x = (y4.x + Dv * xh.x) * (g4.x / (1.f + expf(-g4.x)));
    v.y = (y4.y + Dv * xh.y) * (g4.y / (1.f + expf(-g4.y)));
    v.z = (y4.z + Dv * xh.z) * (g4.z / (1.f + expf(-g4.z)));
    v.w = (y4.w + Dv * xh.w) * (g4.w / (1.f + expf(-g4.w)));
    float s = v.x * v.x + v.y * v.y + v.z * v.z + v.w * v.w;
#pragma unroll
    for (int o = 16; o > 0; o >>= 1) s += __shfl_xor_sync(0xffffffffu, s, o);
    __shared__ float ws[8];
    if ((tid & 31) == 0) ws[tid >> 5] = s;
    __syncthreads();
    float tot = ws[rl * 2] + ws[rl * 2 + 1];
    float sc = rsqrtf(tot * (1.f / EXPC) + 1e-5f);
    float4 gn = *(const float4*)(gnw + c);
    float4 o4 = make_float4(v.x * sc * gn.x, v.y * sc * gn.y,
                            v.z * sc * gn.z, v.w * sc * gn.w);
    store_split4(g_ahi + (size_t)row * EXPC + c, g_alo + (size_t)row * EXPC + c, o4);
}

// ---------------- combine 4 directional outputs -> bf16 split (warp/row, float4) ------
__global__ __launch_bounds__(256)
void combine_kernel()
{
    int wid  = threadIdx.x >> 5;
    int lane = threadIdx.x & 31;
    int bl   = blockIdx.x * 8 + wid;
    if (bl >= NPATCH) return;
    int b = bl / Lseq, l = bl % Lseq;
    int hg = l / WGc, wg = l % WGc;
    int j = wg * HGc + hg;
    size_t base = (size_t)b * Tseq;
    int c = lane * 4;
    float4 v0 = *(const float4*)(g_hn + (base + l) * DMc + c);
    float4 v1 = *(const float4*)(g_hn + (base + Lseq + j) * DMc + c);
    float4 v2 = *(const float4*)(g_hn + (base + 2 * Lseq + (Lseq - 1 - l)) * DMc + c);
    float4 v3 = *(const float4*)(g_hn + (base + 3 * Lseq + (Lseq - 1 - j)) * DMc + c);
    float4 v = make_float4(v0.x + v1.x + v2.x + v3.x,
                           v0.y + v1.y + v2.y + v3.y,
                           v0.z + v1.z + v2.z + v3.z,
                           v0.w + v1.w + v2.w + v3.w);
    store_split4(g_ahi + (size_t)bl * DMc + c, g_alo + (size_t)bl * DMc + c, v);
}

// ---------------- unpatchify to (B,CIN,340,720) ----------------
__global__ void unpatch(float* __restrict__ out)
{
    int idx = blockIdx.x * blockDim.x + threadIdx.x;
    if (idx >= NPATCH * 480) return;
    int xc = idx % 720;
    int t1 = idx / 720;
    int y  = t1 % 340;
    int t2 = t1 / 340;
    int c  = t2 % 3;
    int b  = t2 / 3;
    int hg = y / PHc,  i  = y % PHc;
    int wg = xc / PWc, jj = xc % PWc;
    int l  = hg * WGc + wg;
    out[idx] = g_proj[((size_t)(b * Lseq + l)) * 480 + i * 24 + jj * 3 + c];
}

// ---------------- host orchestration ----------------
static void* sym_addr(const void* sym)
{
    void* p = nullptr;
    cudaGetSymbolAddress(&p, sym);
    return p;
}

extern "C" void kernel_launch(void* const* d_in, const int* in_sizes, int n_in,
                              void* d_out, int out_size)
{
    (void)in_sizes; (void)n_in; (void)out_size;
    const float* x       = (const float*)d_in[0];
    const float* W_pe    = (const float*)d_in[1];
    const float* b_pe    = (const float*)d_in[2];
    const float* norm_w  = (const float*)d_in[3];
    const float* in_w    = (const float*)d_in[4];
    const float* in_b    = (const float*)d_in[5];
    const float* conv_w  = (const float*)d_in[6];
    const float* conv_b  = (const float*)d_in[7];
    const float* dt_bias = (const float*)d_in[8];
    const float* A_log   = (const float*)d_in[9];
    const float* Dp      = (const float*)d_in[10];
    const float* gn_w    = (const float*)d_in[11];
    const float* out_w   = (const float*)d_in[12];
    const float* out_b   = (const float*)d_in[13];
    const float* normf_w = (const float*)d_in[14];
    const float* r1_w    = (const float*)d_in[15];
    const float* r1_b    = (const float*)d_in[16];
    const float* r2_w    = (const float*)d_in[17];
    const float* r2_b    = (const float*)d_in[18];
    float* out = (float*)d_out;

    float* hbuf = (float*)sym_addr(g_h);
    float* hn   = (float*)sym_addr(g_hn);
    float* proj = (float*)sym_addr(g_proj);
    __nv_bfloat16* ahi  = (__nv_bfloat16*)sym_addr(g_ahi);
    __nv_bfloat16* alo  = (__nv_bfloat16*)sym_addr(g_alo);
    __nv_bfloat16* whi  = (__nv_bfloat16*)sym_addr(g_whi);
    __nv_bfloat16* wlo  = (__nv_bfloat16*)sym_addr(g_wlo);
    __nv_bfloat16* wihi = (__nv_bfloat16*)sym_addr(g_wihi);
    __nv_bfloat16* wilo = (__nv_bfloat16*)sym_addr(g_wilo);
    __nv_bfloat16* wohi = (__nv_bfloat16*)sym_addr(g_wohi);
    __nv_bfloat16* wolo = (__nv_bfloat16*)sym_addr(g_wolo);
    __nv_bfloat16* r1hi = (__nv_bfloat16*)sym_addr(g_r1hi);
    __nv_bfloat16* r1lo = (__nv_bfloat16*)sym_addr(g_r1lo);
    __nv_bfloat16* r2hi = (__nv_bfloat16*)sym_addr(g_r2hi);
    __nv_bfloat16* r2lo = (__nv_bfloat16*)sym_addr(g_r2lo);
    __nv_bfloat16* bhi  = (__nv_bfloat16*)sym_addr(g_bhi);
    __nv_bfloat16* blo  = (__nv_bfloat16*)sym_addr(g_blo);
    __nv_bfloat16* phi  = (__nv_bfloat16*)sym_addr(g_pathi);
    __nv_bfloat16* plo  = (__nv_bfloat16*)sym_addr(g_patlo);

    static int smem_set = 0;
    if (!smem_set) {
        cudaFuncSetAttribute(mma_gemm, cudaFuncAttributeMaxDynamicSharedMemorySize, MMA_SMEM);
        smem_set = 1;
    }

    const int MTL = (NPATCH + 127) / 128;  // 96
    const int MT  = (BT + 127) / 128;      // 383

    // ---- upfront weight conversions (all layers, fused launches) ----
    wsplit2<<<(4 * 772 * DMc + 4 * DMc * EXPC + 255) / 256, 256>>>(
        in_w, wihi, wilo, 4 * 772 * DMc, out_w, wohi, wolo, 4 * DMc * EXPC);
    wsplit2<<<(DMc * DMc + 480 * DMc + 255) / 256, 256>>>(
        r1_w, r1hi, r1lo, DMc * DMc, r2_w, r2hi, r2lo, 480 * DMc);
    wconv_pad<<<(128 * 512 + 255) / 256, 256>>>(W_pe, 128, 480, 512);

    // patch embed (padded K=512) with fused 4-direction scatter into g_h
    patch_gather<<<(NPATCH * 512 + 255) / 256, 256>>>(x);
    mma_gemm<<<dim3(1, MTL), 256, MMA_SMEM>>>(phi, plo, whi, wlo, b_pe, nullptr,
                                              hbuf, NPATCH, 512, DMc, DMc, 2);

    for (int l = 0; l < 4; l++) {
        const float* iw = in_w + (size_t)l * 772 * DMc;
        const float* ib = in_b + (size_t)l * 772;
        // rmsnorm + fused dt head (warp-per-row)
        rmsnorm128<<<BT / 8, 256>>>(hbuf, norm_w + l * DMc, nullptr, 1,
                                    iw + 768 * DMc, ib, dt_bias + l * NHC, A_log + l * NHC);
        // e_kernel depends only on dA -> run before the big GEMM (tail hides in ramp)
        e_kernel<<<32, 256>>>();
        mma_gemm<<<dim3(6, MT), 256, MMA_SMEM>>>(ahi, alo,
                                                 wihi + (size_t)l * 772 * DMc,
                                                 wilo + (size_t)l * 772 * DMc,
                                                 ib, nullptr,
                                                 proj, BT, DMc, PROJW, PROJW, 0);
        conv_silu<<<((BT / 4) * 128 + 255) / 256, 256>>>(conv_w + l * 512 * 4,
                                                         conv_b + l * 512);
        scan_partial<<<1024, 128>>>();
        carry_kernel<<<32, 256>>>();
        corr_kernel<<<dim3(6, SEGS - 1, 32), 256>>>();
        gate_norm<<<BT / 4, 256>>>(Dp + l * NHC, gn_w + l * EXPC);
        mma_gemm<<<dim3(1, MT), 256, MMA_SMEM>>>(ahi, alo,
                                                 wohi + (size_t)l * DMc * EXPC,
                                                 wolo + (size_t)l * DMc * EXPC,
                                                 out_b + l * DMc, hbuf,
                                                 hbuf, BT, EXPC, DMc, DMc, 0);
    }

    rmsnorm128<<<BT / 8, 256>>>(hbuf, normf_w, hn, 0, nullptr, nullptr, nullptr, nullptr);
    combine_kernel<<<(NPATCH + 7) / 8, 256>>>();
    // r1: gelu, emits bf16 split into g_bhi/g_blo
    mma_gemm<<<dim3(1, MTL), 256, MMA_SMEM>>>(ahi, alo, r1hi, r1lo, r1_b, nullptr,
                                              proj, NPATCH, DMc, DMc, DMc, 1);
    // r2: 480 outputs into g_proj, then coalesced unpatchify
    mma_gemm<<<dim3(4, MTL), 256, MMA_SMEM>>>(bhi, blo, r2hi, r2lo, r2_b, nullptr,
                                              proj, NPATCH, DMc, 480, 480, 0);
    unpatch<<<(NPATCH * 480 + 255) / 256, 256>>>(out);
}

// round 16
// speedup vs baseline: 1.1662x; 1.0543x over previous
#include <cuda_runtime.h>
#include <cuda_bf16.h>
#include <math.h>
#include <stdint.h>

// ---------------- problem constants ----------------
#define BATCH  8
#define HGc    17
#define WGc    90
#define Lseq   1530            // HG*WG
#define Tseq   6120            // 4*L
#define BT     48960           // BATCH*Tseq
#define DMc    128
#define EXPC   256
#define NHC    4
#define HDC    64
#define PHc    20
#define PWc    8
#define CINc   3
#define NPATCH 12240           // BATCH*Lseq
#define PROJW  768             // gate(256)+xBC(512); dt separate
#define SEGS   8
#define QSEG   765             // Tseq / SEGS

// ---------------- device scratch (static, no allocs) ----------------
__device__ float g_h      [(size_t)BT * DMc];
__device__ float g_proj   [(size_t)BT * PROJW];
__device__ float g_xbc    [(size_t)BT * 512];
__device__ float g_dt     [(size_t)BT * NHC];
__device__ float g_dA     [(size_t)BT * NHC];
__device__ float g_dtx    [(size_t)BT * EXPC];
__device__ float g_y      [(size_t)BT * EXPC];
__device__ float g_e      [(size_t)32 * Tseq];                 // cumprod dA per (b,h)
__device__ float g_spart  [(size_t)32 * SEGS * 64 * 128];      // segment-final partial states
__device__ float g_sinit  [(size_t)32 * SEGS * 64 * 128];      // segment initial states
// bf16 split operand buffers for tensor-core GEMMs
__device__ __nv_bfloat16 g_ahi[(size_t)BT * 256];
__device__ __nv_bfloat16 g_alo[(size_t)BT * 256];
__device__ __nv_bfloat16 g_whi[(size_t)768 * 256];      // patch-embed weight
__device__ __nv_bfloat16 g_wlo[(size_t)768 * 256];
__device__ __nv_bfloat16 g_wihi[(size_t)4 * 772 * DMc]; // in_proj weights (all layers)
__device__ __nv_bfloat16 g_wilo[(size_t)4 * 772 * DMc];
__device__ __nv_bfloat16 g_wohi[(size_t)4 * DMc * EXPC];// out_proj weights (all layers)
__device__ __nv_bfloat16 g_wolo[(size_t)4 * DMc * EXPC];
__device__ __nv_bfloat16 g_r1hi[DMc * DMc];
__device__ __nv_bfloat16 g_r1lo[DMc * DMc];
__device__ __nv_bfloat16 g_r2hi[480 * DMc];
__device__ __nv_bfloat16 g_r2lo[480 * DMc];
__device__ __nv_bfloat16 g_bhi[(size_t)NPATCH * DMc];
__device__ __nv_bfloat16 g_blo[(size_t)NPATCH * DMc];
__device__ __nv_bfloat16 g_pathi[(size_t)NPATCH * 512];
__device__ __nv_bfloat16 g_patlo[(size_t)NPATCH * 512];

__device__ __forceinline__ uint32_t smem_u32(const void* p)
{
    uint32_t a;
    asm("{ .reg .u64 t; cvta.to.shared.u64 t, %1; cvt.u32.u64 %0, t; }"
        : "=r"(a) : "l"(p));
    return a;
}

__device__ __forceinline__ void ldmx4(uint32_t& r0, uint32_t& r1, uint32_t& r2,
                                      uint32_t& r3, uint32_t addr)
{
    asm volatile("ldmatrix.sync.aligned.m8n8.x4.shared.b16 {%0,%1,%2,%3}, [%4];"
                 : "=r"(r0), "=r"(r1), "=r"(r2), "=r"(r3) : "r"(addr));
}

__device__ __forceinline__ void mma_bf16(float* d, const uint32_t* a, const uint32_t* b)
{
    asm volatile(
        "mma.sync.aligned.m16n8k16.row.col.f32.bf16.bf16.f32 "
        "{%0,%1,%2,%3}, {%4,%5,%6,%7}, {%8,%9}, {%0,%1,%2,%3};"
        : "+f"(d[0]), "+f"(d[1]), "+f"(d[2]), "+f"(d[3])
        : "r"(a[0]), "r"(a[1]), "r"(a[2]), "r"(a[3]), "r"(b[0]), "r"(b[1]));
}

// ---------------- f32x2 helpers ----------------
union F4U { float4 f; unsigned long long u[2]; float s[4]; };

__device__ __forceinline__ unsigned long long ffma2(unsigned long long a,
                                                    unsigned long long b,
                                                    unsigned long long c)
{
    unsigned long long d;
    asm("fma.rn.f32x2 %0, %1, %2, %3;" : "=l"(d) : "l"(a), "l"(b), "l"(c));
    return d;
}

__device__ __forceinline__ unsigned long long fmul2(unsigned long long a,
                                                    unsigned long long b)
{
    unsigned long long d;
    asm("mul.rn.f32x2 %0, %1, %2;" : "=l"(d) : "l"(a), "l"(b));
    return d;
}

__device__ __forceinline__ unsigned long long pack2(float lo, float hi)
{
    unsigned long long d;
    asm("mov.b64 %0, {%1, %2};" : "=l"(d) : "f"(lo), "f"(hi));
    return d;
}

__device__ __forceinline__ void unpack2(unsigned long long v, float& lo, float& hi)
{
    asm("mov.b64 {%0, %1}, %2;" : "=f"(lo), "=f"(hi) : "l"(v));
}

// ---------------- pack 4 floats -> 4 bf16 hi + 4 bf16 lo stores ----------------
__device__ __forceinline__ void store_split4(__nv_bfloat16* hi_dst, __nv_bfloat16* lo_dst,
                                             float4 v)
{
    __nv_bfloat16 hh[4], ll[4];
    float vs[4] = {v.x, v.y, v.z, v.w};
#pragma unroll
    for (int i = 0; i < 4; i++) {
        hh[i] = __float2bfloat16(vs[i]);
        ll[i] = __float2bfloat16(vs[i] - __bfloat162float(hh[i]));
    }
    *(uint2*)hi_dst = *(uint2*)hh;
    *(uint2*)lo_dst = *(uint2*)ll;
}

// ---------------- bf16-split tensor-core GEMM (mma.sync) ----------------
// mode 0: C = A@W^T + bias (+resid)
// mode 1: gelu(A@W^T + bias) -> bf16 hi/lo split into g_bhi/g_blo (C unused)
// mode 2: A@W^T + bias scattered into 4 directional rows of C (=g_h)
#define MLDS 72   // smem row pitch in bf16 (144 bytes)

__device__ __forceinline__ void epi_store(int mode, float* C, int ldc,
                                          const float* resid, int row, int col,
                                          float vx, float vy)
{
    if (mode == 1) {
        __nv_bfloat16 hx = __float2bfloat16(vx);
        __nv_bfloat16 hy = __float2bfloat16(vy);
        g_bhi[(size_t)row * ldc + col] = hx;
        g_bhi[(size_t)row * ldc + col + 1] = hy;
        g_blo[(size_t)row * ldc + col] = __float2bfloat16(vx - __bfloat162float(hx));
        g_blo[(size_t)row * ldc + col + 1] = __float2bfloat16(vy - __bfloat162float(hy));
    } else if (mode == 2) {
        int b = row / Lseq, l = row % Lseq;
        int hg = l / WGc, wg = l % WGc;
        int j = wg * HGc + hg;
        size_t base = (size_t)b * Tseq;
        float2 v = make_float2(vx, vy);
        *(float2*)(C + (base + l) * DMc + col) = v;
        *(float2*)(C + (base + Lseq + j) * DMc + col) = v;
        *(float2*)(C + (base + 2 * Lseq + (Lseq - 1 - l)) * DMc + col) = v;
        *(float2*)(C + (base + 3 * Lseq + (Lseq - 1 - j)) * DMc + col) = v;
    } else {
        if (resid) {
            vx += resid[(size_t)row * ldc + col];
            vy += resid[(size_t)row * ldc + col + 1];
        }
        *(float2*)(C + (size_t)row * ldc + col) = make_float2(vx, vy);
    }
}

__global__ __launch_bounds__(256)
void mma_gemm(const __nv_bfloat16* __restrict__ Ahi, const __nv_bfloat16* __restrict__ Alo,
              const __nv_bfloat16* __restrict__ Whi, const __nv_bfloat16* __restrict__ Wlo,
              const float* __restrict__ bias, const float* __restrict__ resid,
              float* __restrict__ C, int M, int Ktot, int N, int ldc, int mode)
{
    extern __shared__ __align__(16) __nv_bfloat16 sm[];
    __nv_bfloat16* sAh = sm;
    __nv_bfloat16* sAl = sAh + 128 * MLDS;
    __nv_bfloat16* sWh = sAl + 128 * MLDS;
    __nv_bfloat16* sWl = sWh + 128 * MLDS;
    const uint32_t bAh = smem_u32(sAh);
    const uint32_t bAl = smem_u32(sAl);
    const uint32_t bWh = smem_u32(sWh);
    const uint32_t bWl = smem_u32(sWl);

    const int tid  = threadIdx.x;
    const int wid  = tid >> 5;
    const int lane = tid & 31;
    const int m0 = blockIdx.y * 128;
    const int n0 = blockIdx.x * 128;
    const int wm = (wid >> 2) * 64;
    const int wn = (wid & 3) * 32;

    float acc[4][4][4];
#pragma unroll
    for (int i = 0; i < 4; i++)
#pragma unroll
        for (int j = 0; j < 4; j++)
#pragma unroll
            for (int q = 0; q < 4; q++) acc[i][j][q] = 0.f;

    const int lrow = tid >> 1;
    const int lcol = (tid & 1) * 32;
    const bool okA = (m0 + lrow) < M;
    const bool okW = (n0 + lrow) < N;
    const uint4 z16 = make_uint4(0u, 0u, 0u, 0u);
    const int lm_row = lane & 15;
    const int lm_col = (lane >> 4) * 8;

    for (int kc = 0; kc < Ktot; kc += 64) {
        if (kc) __syncthreads();
        const uint4* pAh = (const uint4*)(Ahi + (size_t)(m0 + lrow) * Ktot + kc + lcol);
        const uint4* pAl = (const uint4*)(Alo + (size_t)(m0 + lrow) * Ktot + kc + lcol);
        const uint4* pWh = (const uint4*)(Whi + (size_t)(n0 + lrow) * Ktot + kc + lcol);
        const uint4* pWl = (const uint4*)(Wlo + (size_t)(n0 + lrow) * Ktot + kc + lcol);
        uint4* dAh = (uint4*)(sAh + lrow * MLDS + lcol);
        uint4* dAl = (uint4*)(sAl + lrow * MLDS + lcol);
        uint4* dWh = (uint4*)(sWh + lrow * MLDS + lcol);
        uint4* dWl = (uint4*)(sWl + lrow * MLDS + lcol);
#pragma unroll
        for (int q = 0; q < 4; q++) {
            dAh[q] = okA ? pAh[q] : z16;
            dAl[q] = okA ? pAl[q] : z16;
            dWh[q] = okW ? pWh[q] : z16;
            dWl[q] = okW ? pWl[q] : z16;
        }
        __syncthreads();

#pragma unroll
        for (int ks = 0; ks < 4; ks++) {
            const int k0 = ks * 16;
            uint32_t bh[4][2], bl[4][2];
#pragma unroll
            for (int pr = 0; pr < 2; pr++) {
                uint32_t off = (uint32_t)(((wn + pr * 16 + lm_row) * MLDS + k0 + lm_col) * 2);
                uint32_t r0, r1, r2, r3;
                ldmx4(r0, r1, r2, r3, bWh + off);
                bh[pr * 2][0] = r0; bh[pr * 2 + 1][0] = r1;
                bh[pr * 2][1] = r2; bh[pr * 2 + 1][1] = r3;
                ldmx4(r0, r1, r2, r3, bWl + off);
                bl[pr * 2][0] = r0; bl[pr * 2 + 1][0] = r1;
                bl[pr * 2][1] = r2; bl[pr * 2 + 1][1] = r3;
            }
#pragma unroll
            for (int mt = 0; mt < 4; mt++) {
                uint32_t off = (uint32_t)(((wm + mt * 16 + lm_row) * MLDS + k0 + lm_col) * 2);
                uint32_t ah[4], al[4];
                ldmx4(ah[0], ah[1], ah[2], ah[3], bAh + off);
                ldmx4(al[0], al[1], al[2], al[3], bAl + off);
#pragma unroll
                for (int nt = 0; nt < 4; nt++) {
                    mma_bf16(acc[mt][nt], ah, bh[nt]);
                    mma_bf16(acc[mt][nt], ah, bl[nt]);
                    mma_bf16(acc[mt][nt], al, bh[nt]);
                }
            }
        }
    }

    const int gid = lane >> 2;
    const int tig = lane & 3;
#pragma unroll
    for (int mt = 0; mt < 4; mt++) {
        int row0 = m0 + wm + mt * 16 + gid;
        int row1 = row0 + 8;
#pragma unroll
        for (int nt = 0; nt < 4; nt++) {
            int col = n0 + wn + nt * 8 + tig * 2;
            if (col >= N) continue;
            float bx = bias[col];
            float by = bias[col + 1];
            if (row0 < M) {
                float vx = acc[mt][nt][0] + bx, vy = acc[mt][nt][1] + by;
                if (mode == 1) {
                    vx = 0.5f * vx * (1.f + erff(vx * 0.7071067811865475f));
                    vy = 0.5f * vy * (1.f + erff(vy * 0.7071067811865475f));
                }
                epi_store(mode, C, ldc, resid, row0, col, vx, vy);
            }
            if (row1 < M) {
                float vx = acc[mt][nt][2] + bx, vy = acc[mt][nt][3] + by;
                if (mode == 1) {
                    vx = 0.5f * vx * (1.f + erff(vx * 0.7071067811865475f));
                    vy = 0.5f * vy * (1.f + erff(vy * 0.7071067811865475f));
                }
                epi_store(mode, C, ldc, resid, row1, col, vx, vy);
            }
        }
    }
}
#define MMA_SMEM (4 * 128 * MLDS * 2)

// ---------------- weight fp32 -> bf16 hi/lo split (fused pairs) ----------------
__global__ void wsplit2(const float* __restrict__ w1, __nv_bfloat16* __restrict__ h1,
                        __nv_bfloat16* __restrict__ l1, int n1,
                        const float* __restrict__ w2, __nv_bfloat16* __restrict__ h2,
                        __nv_bfloat16* __restrict__ l2, int n2)
{
    int idx = blockIdx.x * blockDim.x + threadIdx.x;
    if (idx < n1) {
        float v = w1[idx];
        __nv_bfloat16 h = __float2bfloat16(v);
        h1[idx] = h;
        l1[idx] = __float2bfloat16(v - __bfloat162float(h));
    } else if (idx < n1 + n2) {
        int k = idx - n1;
        float v = w2[k];
        __nv_bfloat16 h = __float2bfloat16(v);
        h2[k] = h;
        l2[k] = __float2bfloat16(v - __bfloat162float(h));
    }
}

__global__ void wconv_pad(const float* __restrict__ w, int N, int Ksrc, int Kdst)
{
    int idx = blockIdx.x * blockDim.x + threadIdx.x;
    if (idx >= N * Kdst) return;
    int k = idx % Kdst, n = idx / Kdst;
    float v = (k < Ksrc) ? w[n * Ksrc + k] : 0.f;
    __nv_bfloat16 hi = __float2bfloat16(v);
    g_whi[idx] = hi;
    g_wlo[idx] = __float2bfloat16(v - __bfloat162float(hi));
}

// ---------------- patch gather (x8 vectorized, bf16 split, K padded 480->512) --------
__global__ void patch_gather(const float* __restrict__ x)
{
    int idx = blockIdx.x * blockDim.x + threadIdx.x;   // NPATCH * 64
    if (idx >= NPATCH * 64) return;
    int q8 = idx & 63;
    int bl = idx >> 6;
    int q  = q8 * 8;
    float v[8];
    if (q < 480) {
        int c  = q / 160, rr = q % 160;
        int i  = rr >> 3;                 // jj spans 0..7 (full contiguous row)
        int b  = bl / Lseq, l = bl % Lseq;
        int hg = l / WGc,  wg = l % WGc;
        const float* src = x + (((size_t)(b * CINc + c) * 340) + hg * PHc + i) * 720
                             + wg * PWc;
        float4 a = *(const float4*)src;
        float4 d = *(const float4*)(src + 4);
        v[0] = a.x; v[1] = a.y; v[2] = a.z; v[3] = a.w;
        v[4] = d.x; v[5] = d.y; v[6] = d.z; v[7] = d.w;
    } else {
#pragma unroll
        for (int k = 0; k < 8; k++) v[k] = 0.f;
    }
    __nv_bfloat16 hh[8], ll[8];
#pragma unroll
    for (int k = 0; k < 8; k++) {
        hh[k] = __float2bfloat16(v[k]);
        ll[k] = __float2bfloat16(v[k] - __bfloat162float(hh[k]));
    }
    *(uint4*)(g_pathi + (size_t)bl * 512 + q) = *(uint4*)hh;
    *(uint4*)(g_patlo + (size_t)bl * 512 + q) = *(uint4*)ll;
}

// ---------------- rmsnorm: warp per row, float4 per lane, fused dt head ----------------
__global__ __launch_bounds__(256)
void rmsnorm128(const float* __restrict__ X, const float* __restrict__ w,
                int emit_bf16,
                const float* __restrict__ wdt, const float* __restrict__ inb,
                const float* __restrict__ dtb, const float* __restrict__ alog)
{
    int wid  = threadIdx.x >> 5;
    int lane = threadIdx.x & 31;
    int row  = blockIdx.x * 8 + wid;
    float4 vx = *(const float4*)(X + (size_t)row * DMc + lane * 4);
    float s = vx.x * vx.x + vx.y * vx.y + vx.z * vx.z + vx.w * vx.w;
#pragma unroll
    for (int o = 16; o > 0; o >>= 1) s += __shfl_xor_sync(0xffffffffu, s, o);
    float sc = rsqrtf(s * (1.f / DMc) + 1e-5f);
    float4 wv = *(const float4*)(w + lane * 4);
    float4 o4 = make_float4(vx.x * sc * wv.x, vx.y * sc * wv.y,
                            vx.z * sc * wv.z, vx.w * sc * wv.w);
    if (emit_bf16)
        store_split4(g_ahi + (size_t)row * DMc + lane * 4,
                     g_alo + (size_t)row * DMc + lane * 4, o4);
    if (wdt) {
        float dts[4];
#pragma unroll
        for (int h = 0; h < 4; h++) {
            float4 q = *(const float4*)(wdt + h * DMc + lane * 4);
            float t = o4.x * q.x + o4.y * q.y + o4.z * q.z + o4.w * q.w;
#pragma unroll
            for (int o = 16; o > 0; o >>= 1) t += __shfl_xor_sync(0xffffffffu, t, o);
            dts[h] = t;
        }
        if (lane == 0) {
#pragma unroll
            for (int h = 0; h < 4; h++) {
                float xv = dts[h] + inb[768 + h] + dtb[h];
                float sp = (xv > 20.f) ? xv : log1pf(expf(xv));
                g_dt[row * 4 + h] = sp;
                g_dA[row * 4 + h] = expf(-expf(alog[h]) * sp);
            }
        }
    }
}

// ---------------- conv(K=4)+silu, time-tiled x4, fused dtx ----------------
__global__ void conv_silu(const float* __restrict__ cw, const float* __restrict__ cb)
{
    int idx = blockIdx.x * blockDim.x + threadIdx.x;   // (BT/4)*128
    if (idx >= (BT / 4) * 128) return;
    int c4 = idx & 127;
    int q4 = idx >> 7;
    int tq = q4 % (Tseq / 4), b = q4 / (Tseq / 4);
    int t0 = tq * 4;
    int c = c4 * 4;
    float4 bias = *(const float4*)(cb + c);
    float4 w0 = *(const float4*)(cw + (c + 0) * 4);
    float4 w1 = *(const float4*)(cw + (c + 1) * 4);
    float4 w2 = *(const float4*)(cw + (c + 2) * 4);
    float4 w3 = *(const float4*)(cw + (c + 3) * 4);
    const float* base = g_proj + ((size_t)(b * Tseq + t0)) * PROJW + 256 + c;
    float4 in[7];
#pragma unroll
    for (int k = 0; k < 7; k++) {
        int tt = t0 + k - 3;
        in[k] = (tt >= 0) ? *(const float4*)(base + (ptrdiff_t)(k - 3) * PROJW)
                          : make_float4(0.f, 0.f, 0.f, 0.f);
    }
    size_t bt0 = (size_t)b * Tseq + t0;
#pragma unroll
    for (int q = 0; q < 4; q++) {
        float4 acc = bias;
#pragma unroll
        for (int k = 0; k < 4; k++) {
            float4 v = in[q + k];
            acc.x = fmaf(v.x, ((const float*)&w0)[k], acc.x);
            acc.y = fmaf(v.y, ((const float*)&w1)[k], acc.y);
            acc.z = fmaf(v.z, ((const float*)&w2)[k], acc.z);
            acc.w = fmaf(v.w, ((const float*)&w3)[k], acc.w);
        }
        float4 val;
        val.x = acc.x / (1.f + expf(-acc.x));
        val.y = acc.y / (1.f + expf(-acc.y));
        val.z = acc.z / (1.f + expf(-acc.z));
        val.w = acc.w / (1.f + expf(-acc.w));
        *(float4*)(g_xbc + (bt0 + q) * 512 + c) = val;
        if (c4 < 64) {
            float dtv = g_dt[(bt0 + q) * 4 + (c4 >> 4)];
            *(float4*)(g_dtx + (bt0 + q) * EXPC + c) =
                make_float4(val.x * dtv, val.y * dtv, val.z * dtv, val.w * dtv);
        }
    }
}

// ---------------- cumprod of dA within each segment ----------------
__global__ void e_kernel()
{
    int gw   = blockIdx.x * 8 + (threadIdx.x >> 5);   // 0..255 = bh(32) x seg(8)
    int lane = threadIdx.x & 31;
    int bh = gw >> 3, seg = gw & 7;
    int b = bh >> 2, h = bh & 3;
    size_t dbase = ((size_t)b * Tseq + seg * QSEG) * 4 + h;
    float v[24];
    float prod = 1.f;
#pragma unroll
    for (int i = 0; i < 24; i++) {
        int t = lane * 24 + i;
        float d = (t < QSEG) ? g_dA[dbase + (size_t)t * 4] : 1.f;
        prod *= d;
        v[i] = prod;
    }
    float inc = prod;
#pragma unroll
    for (int o = 1; o < 32; o <<= 1) {
        float q = __shfl_up_sync(0xffffffffu, inc, o);
        if (lane >= o) inc *= q;
    }
    float exs = __shfl_up_sync(0xffffffffu, inc, 1);
    if (lane == 0) exs = 1.f;
    size_t ebase = (size_t)bh * Tseq + seg * QSEG;
#pragma unroll
    for (int i = 0; i < 24; i++) {
        int t = lane * 24 + i;
        if (t < QSEG) g_e[ebase + t] = exs * v[i];
    }
}

// ---------------- scan step body (packed f32x2) ----------------
__device__ __forceinline__ void scan_step(unsigned long long s[4][2],
                                          const F4U& bn, const F4U& cn, const F4U& x0,
                                          float d0, float* yp, bool doStore)
{
    unsigned long long dp = pack2(d0, d0);
    float a[4];
#pragma unroll
    for (int i = 0; i < 4; i++) {
        unsigned long long xp = pack2(x0.s[i], x0.s[i]);
        s[i][0] = ffma2(s[i][0], dp, fmul2(xp, bn.u[0]));
        s[i][1] = ffma2(s[i][1], dp, fmul2(xp, bn.u[1]));
        unsigned long long m = fmul2(s[i][0], cn.u[0]);
        m = ffma2(s[i][1], cn.u[1], m);
        float lo, hi;
        unpack2(m, lo, hi);
        a[i] = lo + hi;
    }
    int lane = threadIdx.x & 31;
    a[0] += __shfl_xor_sync(0xffffffffu, a[0], 16);
    a[1] += __shfl_xor_sync(0xffffffffu, a[1], 16);
    a[2] += __shfl_xor_sync(0xffffffffu, a[2], 16);
    a[3] += __shfl_xor_sync(0xffffffffu, a[3], 16);
    float b0 = (lane & 16) ? a[2] : a[0];
    float b1 = (lane & 16) ? a[3] : a[1];
    b0 += __shfl_xor_sync(0xffffffffu, b0, 8);
    b1 += __shfl_xor_sync(0xffffffffu, b1, 8);
    float c0 = (lane & 8) ? b1 : b0;
    c0 += __shfl_xor_sync(0xffffffffu, c0, 4);
    c0 += __shfl_xor_sync(0xffffffffu, c0, 2);
    c0 += __shfl_xor_sync(0xffffffffu, c0, 1);
    if (doStore) *yp = c0;
}

// ---------------- phase 1: partial scans per segment (4 p per warp) ----------------
__global__ __launch_bounds__(128)
void scan_partial()
{
    int bid  = blockIdx.x;            // 1024 = b(8) h(4) seg(8) pb(4)
    int b    = bid >> 7;
    int h    = (bid >> 5) & 3;
    int seg  = (bid >> 2) & 7;
    int pb   = bid & 3;
    int widx = threadIdx.x >> 5;
    int lane = threadIdx.x & 31;
    int p    = pb * 16 + widx * 4;
    int t0   = seg * QSEG;

    const float* dAp = g_dA + ((size_t)b * Tseq + t0) * NHC + h;
    const F4U*   Xp  = (const F4U*)(g_dtx + ((size_t)b * Tseq + t0) * EXPC + h * HDC + p);
    const F4U*   Bp  = (const F4U*)(g_xbc + ((size_t)b * Tseq + t0) * 512 + 256) + lane;
    const F4U*   Cp  = (const F4U*)(g_xbc + ((size_t)b * Tseq + t0) * 512 + 384) + lane;
    int plocal = ((lane >> 4) << 1) | ((lane >> 3) & 1);
    float* yp = g_y + ((size_t)b * Tseq + t0) * EXPC + h * HDC + p + plocal;
    bool doStore = ((lane & 7) == 0);

    unsigned long long s[4][2];
#pragma unroll
    for (int i = 0; i < 4; i++) { s[i][0] = 0ull; s[i][1] = 0ull; }

    F4U bv, cv, xx;
    bv = *Bp; cv = *Cp; xx = *Xp;
    float da = *dAp;
    for (int t = 0; t < QSEG - 1; t++) {
        Bp += 128; Cp += 128; Xp += 64; dAp += 4;
        F4U bn = bv, cn = cv, x0 = xx;
        float d0 = da;
        bv = *Bp; cv = *Cp; xx = *Xp; da = *dAp;
        scan_step(s, bn, cn, x0, d0, yp, doStore);
        yp += EXPC;
    }
    scan_step(s, bv, cv, xx, da, yp, doStore);

    int bh = b * 4 + h;
    size_t sb = ((size_t)bh * SEGS + seg) * 64 + p;
#pragma unroll
    for (int i = 0; i < 4; i++) {
        F4U sv;
        sv.u[0] = s[i][0]; sv.u[1] = s[i][1];
        ((float4*)(g_spart + (sb + i) * 128))[lane] = sv.f;
    }
}

// ---------------- phase 2: carry initial states across segments (widened 8x) ---------
__global__ void carry_kernel()
{
    int bh = blockIdx.x;       // (32, 8) grid
    int kq = blockIdx.y;       // quarter 0..7
    int tid = threadIdx.x;     // 256
    __shared__ float Ps[SEGS];
    if (tid < SEGS) Ps[tid] = g_e[(size_t)bh * Tseq + (size_t)(tid + 1) * QSEG - 1];
    __syncthreads();
    for (int k = kq * 4; k < kq * 4 + 4; k++) {
        int idx = tid + k * 256;  // p*128+n
        float sini = 0.f;
#pragma unroll
        for (int s = 1; s < SEGS; s++) {
            sini = g_spart[((size_t)bh * SEGS + (s - 1)) * 8192 + idx] + sini * Ps[s - 1];
            g_sinit[((size_t)bh * SEGS + s) * 8192 + idx] = sini;
        }
    }
}

// ---------------- phase 3: y[t,p] += e_t * (C_t . S_init) ----------------
#define BK 16
__global__ __launch_bounds__(256)
void corr_kernel()
{
    int mt  = blockIdx.x;            // 0..5
    int seg = blockIdx.y + 1;        // 1..7
    int bh  = blockIdx.z;            // 0..31
    int b = bh >> 2, h = bh & 3;
    int t0 = seg * QSEG + mt * 128;
    if (g_e[(size_t)bh * Tseq + t0] == 0.f) return;

    __shared__ __align__(16) float Cs[BK][132];
    __shared__ __align__(16) float Ss[BK][68];
    const int tid = threadIdx.x;
    const int tx = tid & 15;
    const int ty = tid >> 4;
    const int lr = tid >> 2;
    const int lc = (tid & 3) << 2;

    const float* Abase = g_xbc + ((size_t)(b * Tseq + t0)) * 512 + 384;
    const float* Sbase = g_sinit + ((size_t)bh * SEGS + seg) * 8192;
    float acc[8][4];
#pragma unroll
    for (int i = 0; i < 8; i++)
#pragma unroll
        for (int j = 0; j < 4; j++) acc[i][j] = 0.f;

    const int mlim = QSEG - mt * 128;
    for (int k0 = 0; k0 < 128; k0 += BK) {
        float4 va = (lr < mlim) ? *(const float4*)(Abase + (size_t)lr * 512 + k0 + lc)
                                : make_float4(0.f, 0.f, 0.f, 0.f);
        float4 vb = (lr + 64 < mlim) ? *(const float4*)(Abase + (size_t)(lr + 64) * 512 + k0 + lc)
                                     : make_float4(0.f, 0.f, 0.f, 0.f);
        float4 vs = *(const float4*)(Sbase + (size_t)lr * 128 + k0 + lc);
        __syncthreads();
        Cs[lc + 0][lr] = va.x; Cs[lc + 1][lr] = va.y; Cs[lc + 2][lr] = va.z; Cs[lc + 3][lr] = va.w;
        Cs[lc + 0][lr + 64] = vb.x; Cs[lc + 1][lr + 64] = vb.y;
        Cs[lc + 2][lr + 64] = vb.z; Cs[lc + 3][lr + 64] = vb.w;
        Ss[lc + 0][lr] = vs.x; Ss[lc + 1][lr] = vs.y; Ss[lc + 2][lr] = vs.z; Ss[lc + 3][lr] = vs.w;
        __syncthreads();
#pragma unroll
        for (int kk = 0; kk < BK; kk++) {
            float4 a0 = *(const float4*)&Cs[kk][ty * 8];
            float4 a1 = *(const float4*)&Cs[kk][ty * 8 + 4];
            float4 bq = *(const float4*)&Ss[kk][tx * 4];
            float av[8] = {a0.x, a0.y, a0.z, a0.w, a1.x, a1.y, a1.z, a1.w};
            float bw[4] = {bq.x, bq.y, bq.z, bq.w};
#pragma unroll
            for (int i = 0; i < 8; i++)
#pragma unroll
                for (int j = 0; j < 4; j++)
                    acc[i][j] = fmaf(av[i], bw[j], acc[i][j]);
        }
    }
#pragma unroll
    for (int i = 0; i < 8; i++) {
        int mrow = ty * 8 + i;
        if (mrow >= mlim) continue;
        int tg = t0 + mrow;
        float e = g_e[(size_t)bh * Tseq + tg];
        float* yd = g_y + ((size_t)(b * Tseq + tg)) * EXPC + h * 64 + tx * 4;
        float4 old = *(float4*)yd;
        old.x += e * acc[i][0];
        old.y += e * acc[i][1];
        old.z += e * acc[i][2];
        old.w += e * acc[i][3];
        *(float4*)yd = old;
    }
}

// ---------------- gate_norm: 4 rows/block, 2 warps/row, float4 ----------------
__global__ __launch_bounds__(256)
void gate_norm(const float* __restrict__ Dp, const float* __restrict__ gnw)
{
    int tid = threadIdx.x;
    int rl  = tid >> 6;                 // row within block 0..3
    int row = blockIdx.x * 4 + rl;
    int ci  = tid & 63;                 // float4 index within row
    int c   = ci * 4;
    float4 xh = *(const float4*)(g_xbc + (size_t)row * 512 + c);
    float4 y4 = *(const float4*)(g_y + (size_t)row * EXPC + c);
    float4 g4 = *(const float4*)(g_proj + (size_t)row * PROJW + c);
    float Dv = Dp[c >> 6];
    float4 v;
    v.x = (y4.x + Dv * xh.x) * (g4.x / (1.f + expf(-g4.x)));
    v.y = (y4.y + Dv * xh.y) * (g4.y / (1.f + expf(-g4.y)));
    v.z = (y4.z + Dv * xh.z) * (g4.z / (1.f + expf(-g4.z)));
    v.w = (y4.w + Dv * xh.w) * (g4.w / (1.f + expf(-g4.w)));
    float s = v.x * v.x + v.y * v.y + v.z * v.z + v.w * v.w;
#pragma unroll
    for (int o = 16; o > 0; o >>= 1) s += __shfl_xor_sync(0xffffffffu, s, o);
    __shared__ float ws[8];
    if ((tid & 31) == 0) ws[tid >> 5] = s;
    __syncthreads();
    float tot = ws[rl * 2] + ws[rl * 2 + 1];
    float sc = rsqrtf(tot * (1.f / EXPC) + 1e-5f);
    float4 gn = *(const float4*)(gnw + c);
    float4 o4 = make_float4(v.x * sc * gn.x, v.y * sc * gn.y,
                            v.z * sc * gn.z, v.w * sc * gn.w);
    store_split4(g_ahi + (size_t)row * EXPC + c, g_alo + (size_t)row * EXPC + c, o4);
}

// ---------------- fused final rmsnorm + combine -> bf16 split (warp/row) --------------
__global__ __launch_bounds__(256)
void combine_fused(const float* __restrict__ wf)
{
    int wid  = threadIdx.x >> 5;
    int lane = threadIdx.x & 31;
    int bl   = blockIdx.x * 8 + wid;
    if (bl >= NPATCH) return;
    int b = bl / Lseq, l = bl % Lseq;
    int hg = l / WGc, wg = l % WGc;
    int j = wg * HGc + hg;
    size_t base = (size_t)b * Tseq;
    int c = lane * 4;
    size_t r0 = (base + l) * DMc;
    size_t r1 = (base + Lseq + j) * DMc;
    size_t r2 = (base + 2 * Lseq + (Lseq - 1 - l)) * DMc;
    size_t r3 = (base + 3 * Lseq + (Lseq - 1 - j)) * DMc;
    float4 v0 = *(const float4*)(g_h + r0 + c);
    float4 v1 = *(const float4*)(g_h + r1 + c);
    float4 v2 = *(const float4*)(g_h + r2 + c);
    float4 v3 = *(const float4*)(g_h + r3 + c);
    float s0 = v0.x * v0.x + v0.y * v0.y + v0.z * v0.z + v0.w * v0.w;
    float s1 = v1.x * v1.x + v1.y * v1.y + v1.z * v1.z + v1.w * v1.w;
    float s2 = v2.x * v2.x + v2.y * v2.y + v2.z * v2.z + v2.w * v2.w;
    float s3 = v3.x * v3.x + v3.y * v3.y + v3.z * v3.z + v3.w * v3.w;
#pragma unroll
    for (int o = 16; o > 0; o >>= 1) {
        s0 += __shfl_xor_sync(0xffffffffu, s0, o);
        s1 += __shfl_xor_sync(0xffffffffu, s1, o);
        s2 += __shfl_xor_sync(0xffffffffu, s2, o);
        s3 += __shfl_xor_sync(0xffffffffu, s3, o);
    }
    float c0 = rsqrtf(s0 * (1.f / DMc) + 1e-5f);
    float c1 = rsqrtf(s1 * (1.f / DMc) + 1e-5f);
    float c2 = rsqrtf(s2 * (1.f / DMc) + 1e-5f);
    float c3 = rsqrtf(s3 * (1.f / DMc) + 1e-5f);
    float4 w4 = *(const float4*)(wf + c);
    float4 v;
    v.x = (v0.x * c0 + v1.x * c1 + v2.x * c2 + v3.x * c3) * w4.x;
    v.y = (v0.y * c0 + v1.y * c1 + v2.y * c2 + v3.y * c3) * w4.y;
    v.z = (v0.z * c0 + v1.z * c1 + v2.z * c2 + v3.z * c3) * w4.z;
    v.w = (v0.w * c0 + v1.w * c1 + v2.w * c2 + v3.w * c3) * w4.w;
    store_split4(g_ahi + (size_t)bl * DMc + c, g_alo + (size_t)bl * DMc + c, v);
}

// ---------------- unpatchify to (B,CIN,340,720) ----------------
__global__ void unpatch(float* __restrict__ out)
{
    int idx = blockIdx.x * blockDim.x + threadIdx.x;
    if (idx >= NPATCH * 480) return;
    int xc = idx % 720;
    int t1 = idx / 720;
    int y  = t1 % 340;
    int t2 = t1 / 340;
    int c  = t2 % 3;
    int b  = t2 / 3;
    int hg = y / PHc,  i  = y % PHc;
    int wg = xc / PWc, jj = xc % PWc;
    int l  = hg * WGc + wg;
    out[idx] = g_proj[((size_t)(b * Lseq + l)) * 480 + i * 24 + jj * 3 + c];
}

// ---------------- host orchestration ----------------
static void* sym_addr(const void* sym)
{
    void* p = nullptr;
    cudaGetSymbolAddress(&p, sym);
    return p;
}

extern "C" void kernel_launch(void* const* d_in, const int* in_sizes, int n_in,
                              void* d_out, int out_size)
{
    (void)in_sizes; (void)n_in; (void)out_size;
    const float* x       = (const float*)d_in[0];
    const float* W_pe    = (const float*)d_in[1];
    const float* b_pe    = (const float*)d_in[2];
    const float* norm_w  = (const float*)d_in[3];
    const float* in_w    = (const float*)d_in[4];
    const float* in_b    = (const float*)d_in[5];
    const float* conv_w  = (const float*)d_in[6];
    const float* conv_b  = (const float*)d_in[7];
    const float* dt_bias = (const float*)d_in[8];
    const float* A_log   = (const float*)d_in[9];
    const float* Dp      = (const float*)d_in[10];
    const float* gn_w    = (const float*)d_in[11];
    const float* out_w   = (const float*)d_in[12];
    const float* out_b   = (const float*)d_in[13];
    const float* normf_w = (const float*)d_in[14];
    const float* r1_w    = (const float*)d_in[15];
    const float* r1_b    = (const float*)d_in[16];
    const float* r2_w    = (const float*)d_in[17];
    const float* r2_b    = (const float*)d_in[18];
    float* out = (float*)d_out;

    float* hbuf = (float*)sym_addr(g_h);
    float* proj = (float*)sym_addr(g_proj);
    __nv_bfloat16* ahi  = (__nv_bfloat16*)sym_addr(g_ahi);
    __nv_bfloat16* alo  = (__nv_bfloat16*)sym_addr(g_alo);
    __nv_bfloat16* whi  = (__nv_bfloat16*)sym_addr(g_whi);
    __nv_bfloat16* wlo  = (__nv_bfloat16*)sym_addr(g_wlo);
    __nv_bfloat16* wihi = (__nv_bfloat16*)sym_addr(g_wihi);
    __nv_bfloat16* wilo = (__nv_bfloat16*)sym_addr(g_wilo);
    __nv_bfloat16* wohi = (__nv_bfloat16*)sym_addr(g_wohi);
    __nv_bfloat16* wolo = (__nv_bfloat16*)sym_addr(g_wolo);
    __nv_bfloat16* r1hi = (__nv_bfloat16*)sym_addr(g_r1hi);
    __nv_bfloat16* r1lo = (__nv_bfloat16*)sym_addr(g_r1lo);
    __nv_bfloat16* r2hi = (__nv_bfloat16*)sym_addr(g_r2hi);
    __nv_bfloat16* r2lo = (__nv_bfloat16*)sym_addr(g_r2lo);
    __nv_bfloat16* bhi  = (__nv_bfloat16*)sym_addr(g_bhi);
    __nv_bfloat16* blo  = (__nv_bfloat16*)sym_addr(g_blo);
    __nv_bfloat16* phi  = (__nv_bfloat16*)sym_addr(g_pathi);
    __nv_bfloat16* plo  = (__nv_bfloat16*)sym_addr(g_patlo);

    static int smem_set = 0;
    if (!smem_set) {
        cudaFuncSetAttribute(mma_gemm, cudaFuncAttributeMaxDynamicSharedMemorySize, MMA_SMEM);
        smem_set = 1;
    }

    const int MTL = (NPATCH + 127) / 128;  // 96
    const int MT  = (BT + 127) / 128;      // 383

    // ---- upfront weight conversions (all layers, fused launches) ----
    wsplit2<<<(4 * 772 * DMc + 4 * DMc * EXPC + 255) / 256, 256>>>(
        in_w, wihi, wilo, 4 * 772 * DMc, out_w, wohi, wolo, 4 * DMc * EXPC);
    wsplit2<<<(DMc * DMc + 480 * DMc + 255) / 256, 256>>>(
        r1_w, r1hi, r1lo, DMc * DMc, r2_w, r2hi, r2lo, 480 * DMc);
    wconv_pad<<<(128 * 512 + 255) / 256, 256>>>(W_pe, 128, 480, 512);

    // patch embed (padded K=512) with fused 4-direction scatter into g_h
    patch_gather<<<(NPATCH * 64 + 255) / 256, 256>>>(x);
    mma_gemm<<<dim3(1, MTL), 256, MMA_SMEM>>>(phi, plo, whi, wlo, b_pe, nullptr,
                                              hbuf, NPATCH, 512, DMc, DMc, 2);

    for (int l = 0; l < 4; l++) {
        const float* iw = in_w + (size_t)l * 772 * DMc;
        const float* ib = in_b + (size_t)l * 772;
        // rmsnorm + fused dt head (warp-per-row)
        rmsnorm128<<<BT / 8, 256>>>(hbuf, norm_w + l * DMc, 1,
                                    iw + 768 * DMc, ib, dt_bias + l * NHC, A_log + l * NHC);
        // e_kernel depends only on dA -> run before the big GEMM (tail hides in ramp)
        e_kernel<<<32, 256>>>();
        mma_gemm<<<dim3(6, MT), 256, MMA_SMEM>>>(ahi, alo,
                                                 wihi + (size_t)l * 772 * DMc,
                                                 wilo + (size_t)l * 772 * DMc,
                                                 ib, nullptr,
                                                 proj, BT, DMc, PROJW, PROJW, 0);
        conv_silu<<<((BT / 4) * 128 + 255) / 256, 256>>>(conv_w + l * 512 * 4,
                                                         conv_b + l * 512);
        scan_partial<<<1024, 128>>>();
        carry_kernel<<<dim3(32, 8), 256>>>();
        corr_kernel<<<dim3(6, SEGS - 1, 32), 256>>>();
        gate_norm<<<BT / 4, 256>>>(Dp + l * NHC, gn_w + l * EXPC);
        mma_gemm<<<dim3(1, MT), 256, MMA_SMEM>>>(ahi, alo,
                                                 wohi + (size_t)l * DMc * EXPC,
                                                 wolo + (size_t)l * DMc * EXPC,
                                                 out_b + l * DMc, hbuf,
                                                 hbuf, BT, EXPC, DMc, DMc, 0);
    }

    // fused final rmsnorm + 4-direction combine -> bf16 split operands
    combine_fused<<<(NPATCH + 7) / 8, 256>>>(normf_w);
    // r1: gelu, emits bf16 split into g_bhi/g_blo
    mma_gemm<<<dim3(1, MTL), 256, MMA_SMEM>>>(ahi, alo, r1hi, r1lo, r1_b, nullptr,
                                              proj, NPATCH, DMc, DMc, DMc, 1);
    // r2: 480 outputs into g_proj, then coalesced unpatchify
    mma_gemm<<<dim3(4, MTL), 256, MMA_SMEM>>>(bhi, blo, r2hi, r2lo, r2_b, nullptr,
                                              proj, NPATCH, DMc, 480, 480, 0);
    unpatch<<<(NPATCH * 480 + 255) / 256, 256>>>(out);
}